// round 7
// baseline (speedup 1.0000x reference)
#include <cuda_runtime.h>
#include <cuda_fp16.h>
#include <cstdint>

#define NN 40000
#define NP 40064   // 313 * 128, padded row count
#define NE 320000
#define NG 64
#define IND 128
#define H4 256
#define OUTD 128
#define CAT 512

// ---------------- scratch (device globals; no allocation allowed) ----------------
__device__ int   g_outcnt[NN];
__device__ int   g_incnt[NN];
__device__ int   g_cursor[NN];
__device__ int   g_rowptr[NN + 1];
__device__ int   g_bsum[64];
__device__ float g_outinv[NN];
__device__ float g_ininv[NN];
__device__ int   g_es[NE];
__device__ float g_ec[NE];
__device__ float g_f1[NP * H4];
__device__ float g_readout[NG * OUTD];
// fp16 activations (padded to NP rows)
__device__ __half g_xh[NP * IND];    // x as fp16
__device__ __half g_a1[NP * IND];    // agg1
__device__ __half g_c[NP * CAT];     // concat [x1 | f1]
__device__ __half g_y2[NP * H4];     // layer2 GEMM out (pre-agg), fp16
__device__ __half g_x2[NP * H4];     // x2
__device__ __half g_y3[NP * OUTD];   // layer3 GEMM out (pre-agg), fp16
// weights split to fp16 hi/lo, transposed to [N][K]
// layout: W1 @0 (32768), fc1 @32768 (32768), W2 @65536 (131072), W3 @196608 (32768)
__device__ __half g_bh[229376];
__device__ __half g_bl[229376];

// ---------------- helpers ----------------
__device__ __forceinline__ uint32_t smem_u32(const void* p) {
    uint32_t a;
    asm("{ .reg .u64 t; cvta.to.shared.u64 t, %1; cvt.u32.u64 %0, t; }" : "=r"(a) : "l"(p));
    return a;
}
__device__ __forceinline__ void cpa16(uint32_t dst, const void* src) {
    asm volatile("cp.async.cg.shared.global [%0], [%1], 16;" :: "r"(dst), "l"(src) : "memory");
}
__device__ __forceinline__ void cpa_commit() {
    asm volatile("cp.async.commit_group;" ::: "memory");
}
__device__ __forceinline__ void cpa_wait0() {
    asm volatile("cp.async.wait_group 0;" ::: "memory");
}
#define MMA16816(d, a, b)                                                     \
    asm volatile(                                                             \
        "mma.sync.aligned.m16n8k16.row.col.f32.f16.f16.f32 "                  \
        "{%0,%1,%2,%3}, {%4,%5,%6,%7}, {%8,%9}, {%0,%1,%2,%3};"               \
        : "+f"((d)[0]), "+f"((d)[1]), "+f"((d)[2]), "+f"((d)[3])              \
        : "r"((a)[0]), "r"((a)[1]), "r"((a)[2]), "r"((a)[3]),                 \
          "r"((b)[0]), "r"((b)[1]))
#define LDSM4(R, addr)                                                        \
    asm volatile("ldmatrix.sync.aligned.m8n8.x4.shared.b16 {%0,%1,%2,%3}, [%4];" \
        : "=r"((R)[0]), "=r"((R)[1]), "=r"((R)[2]), "=r"((R)[3]) : "r"(addr))

__device__ __forceinline__ void hsplit(float v, __half& h, __half& l) {
    h = __float2half_rn(v);
    l = __float2half_rn(v - __half2float(h));
}

// ---------------- setup kernels ----------------
__global__ void k_zero() {
    int i = blockIdx.x * blockDim.x + threadIdx.x;
    if (i < NN) { g_outcnt[i] = 0; g_incnt[i] = 0; g_cursor[i] = 0; }
    if (i < NG * OUTD) g_readout[i] = 0.f;
}

__global__ void k_deg(const int* __restrict__ src, const int* __restrict__ dst) {
    int e = blockIdx.x * blockDim.x + threadIdx.x;
    if (e < NE) {
        atomicAdd(&g_outcnt[src[e]], 1);
        atomicAdd(&g_incnt[dst[e]], 1);
    }
}

// per-block scan (+ merged inv computation)
__global__ void k_scan_a() {
    __shared__ int sh[1024];
    int b = blockIdx.x, t = threadIdx.x;
    int idx = b * 1024 + t;
    int v = (idx < NN) ? g_incnt[idx] : 0;
    if (idx < NN) {
        g_ininv[idx]  = rsqrtf((float)max(v, 1));
        g_outinv[idx] = rsqrtf((float)max(g_outcnt[idx], 1));
    }
    sh[t] = v;
    __syncthreads();
#pragma unroll
    for (int off = 1; off < 1024; off <<= 1) {
        int u = (t >= off) ? sh[t - off] : 0;
        __syncthreads();
        sh[t] += u;
        __syncthreads();
    }
    int incl = sh[t];
    if (idx <= NN) g_rowptr[idx] = incl - v;
    if (t == 1023) g_bsum[b] = incl;
}
// add block-prefix offsets (inline <=40-element prefix)
__global__ void k_scan_c() {
    __shared__ int pre;
    int b = blockIdx.x, t = threadIdx.x;
    if (t == 0) {
        int s = 0;
        for (int i = 0; i < b; i++) s += g_bsum[i];
        pre = s;
    }
    __syncthreads();
    int idx = b * 1024 + t;
    if (idx <= NN) g_rowptr[idx] += pre;
}

__global__ void k_place(const int* __restrict__ src, const int* __restrict__ dst,
                        const float* __restrict__ w) {
    int e = blockIdx.x * blockDim.x + threadIdx.x;
    if (e >= NE) return;
    float4 ww = *(const float4*)(w + 4 * e);
    float m = fmaxf(fmaxf(ww.x, ww.y), fmaxf(ww.z, ww.w));
    int d = dst[e];
    int s = src[e];
    int pos = g_rowptr[d] + atomicAdd(&g_cursor[d], 1);
    g_es[pos] = s;
    g_ec[pos] = m * g_outinv[s];
}

// weights fp32 [K][N] -> fp16 hi/lo [N][K]  AND  x -> fp16 plane, one kernel
#define WTOT 229376
__global__ void k_conv_all(const float* __restrict__ W1, const float* __restrict__ F1,
                           const float* __restrict__ W2, const float* __restrict__ W3,
                           const float* __restrict__ x) {
    int idx = blockIdx.x * blockDim.x + threadIdx.x;
    if (idx < WTOT) {
        const float* W; int K, N, base;
        if (idx < 32768)       { W = W1; K = 128; N = 256; base = 0; }
        else if (idx < 65536)  { W = F1; K = 128; N = 256; base = 32768; }
        else if (idx < 196608) { W = W2; K = 512; N = 256; base = 65536; }
        else                   { W = W3; K = 256; N = 128; base = 196608; }
        int li = idx - base;
        int k = li % K, n = li / K;
        float v = W[k * N + n];
        __half h, l;
        hsplit(v, h, l);
        g_bh[idx] = h;
        g_bl[idx] = l;
    } else {
        int j = idx - WTOT;
        if (j < NP * IND) {
            float v = (j < NN * IND) ? x[j] : 0.f;
            g_xh[j] = __float2half_rn(v);
        }
    }
}

// ---------------- aggregation: one warp per dst node, fp16 gather ----------------
// MODE 0: fp16 out (no relu); MODE 1: relu + fp16 out; MODE 2: relu + readout atomics
// D=128: lane owns 4 dims (uint2); D=256: lane owns 8 dims (uint4)
template <int D, int MODE>
__global__ void k_agg(const __half* __restrict__ in, __half* __restrict__ oh,
                      const int* __restrict__ gid) {
    int warp = (blockIdx.x * blockDim.x + threadIdx.x) >> 5;
    int lane = threadIdx.x & 31;
    if (warp >= NP) return;
    constexpr int V = D / 64;  // half2 units per lane (2 for 128, 4 for 256)
    if (warp >= NN) {  // pad rows: zero plane
        if (MODE != 2) {
            uint32_t* ph = (uint32_t*)(oh + (size_t)warp * D);
#pragma unroll
            for (int v = 0; v < V; v++) ph[lane * V + v] = 0;
        }
        return;
    }
    int beg = g_rowptr[warp];
    int end = g_rowptr[warp + 1];
    float2 acc[V];
#pragma unroll
    for (int v = 0; v < V; v++) acc[v] = make_float2(0.f, 0.f);
    int e = beg;
    for (; e + 1 < end; e += 2) {  // 2-way unroll for MLP
        int s0 = g_es[e], s1 = g_es[e + 1];
        float c0 = g_ec[e], c1 = g_ec[e + 1];
        const uint32_t* p0 = (const uint32_t*)(in + (size_t)s0 * D) + lane * V;
        const uint32_t* p1 = (const uint32_t*)(in + (size_t)s1 * D) + lane * V;
        uint32_t t0[V], t1[V];
#pragma unroll
        for (int v = 0; v < V; v++) { t0[v] = p0[v]; t1[v] = p1[v]; }
#pragma unroll
        for (int v = 0; v < V; v++) {
            float2 f0 = __half22float2(*(const __half2*)&t0[v]);
            float2 f1 = __half22float2(*(const __half2*)&t1[v]);
            acc[v].x = fmaf(c0, f0.x, fmaf(c1, f1.x, acc[v].x));
            acc[v].y = fmaf(c0, f0.y, fmaf(c1, f1.y, acc[v].y));
        }
    }
    if (e < end) {
        int s = g_es[e];
        float c = g_ec[e];
        const uint32_t* p = (const uint32_t*)(in + (size_t)s * D) + lane * V;
#pragma unroll
        for (int v = 0; v < V; v++) {
            uint32_t t = p[v];
            float2 f = __half22float2(*(const __half2*)&t);
            acc[v].x = fmaf(c, f.x, acc[v].x);
            acc[v].y = fmaf(c, f.y, acc[v].y);
        }
    }
    float inv = g_ininv[warp];
#pragma unroll
    for (int v = 0; v < V; v++) {
        acc[v].x *= inv; acc[v].y *= inv;
        if (MODE >= 1) {
            acc[v].x = fmaxf(acc[v].x, 0.f);
            acc[v].y = fmaxf(acc[v].y, 0.f);
        }
    }
    if (MODE == 2) {
        int g = gid[warp];
        float* r = g_readout + g * OUTD + lane * 4;
        atomicAdd(r + 0, acc[0].x);
        atomicAdd(r + 1, acc[0].y);
        atomicAdd(r + 2, acc[1].x);
        atomicAdd(r + 3, acc[1].y);
    } else {
        uint32_t* ph = (uint32_t*)(oh + (size_t)warp * D);
#pragma unroll
        for (int v = 0; v < V; v++) {
            __half2 a = __floats2half2_rn(acc[v].x, acc[v].y);
            ph[lane * V + v] = *(uint32_t*)&a;
        }
    }
}

// ---------------- fp16 2-term mma.sync GEMM ----------------
// C[M,N] = A@(Bh+Bl), A single fp16 plane, B split fp16 hi/lo, fp32 accum.
// Block tile 128x128, BK=32 per stage, 2-stage cp.async pipeline, 80B-padded smem rows.
// EPI: 0 = raw fp32 out, 1 = relu + fp16 out, 2 = raw fp16 out
template <int K, int EPI>
__global__ __launch_bounds__(256, 2) void k_mma(
    const __half* __restrict__ Ah,
    const __half* __restrict__ Bh, const __half* __restrict__ Bl,
    float* __restrict__ C, __half* __restrict__ Ch, int ldC, int colOff) {
    extern __shared__ __align__(16) uint8_t smem[];
    constexpr int NC = K / 32;
    constexpr uint32_t AH_ = 0, BH_ = 10240, BL_ = 20480, STG = 30720;
    const int tid = threadIdx.x;
    const int wid = tid >> 5, lane = tid & 31;
    const int wm = wid & 3, wn = wid >> 2;
    const int m0 = blockIdx.x * 128;
    const int nblk = blockIdx.y * 128;
    const uint32_t sb = smem_u32(smem);

    float acc[2][8][4];
#pragma unroll
    for (int mi = 0; mi < 2; mi++)
#pragma unroll
        for (int ni = 0; ni < 8; ni++)
#pragma unroll
            for (int r = 0; r < 4; r++) acc[mi][ni][r] = 0.f;

    const int arow = tid >> 1, ah_ = tid & 1;
    const __half* aS = Ah + (size_t)(m0 + arow) * K + ah_ * 16;
    const uint32_t aD = AH_ + (uint32_t)arow * 80 + ah_ * 32;
    const int brow = tid & 127, bpl = tid >> 7;
    const __half* bS = (bpl ? Bl : Bh) + (size_t)(nblk + brow) * K;
    const uint32_t bD = (bpl ? BL_ : BH_) + (uint32_t)brow * 80;

    const uint32_t aoff = AH_ + (uint32_t)(wm * 32 + (lane & 7) + ((lane >> 3) & 1) * 8) * 80 +
                          (lane >> 4) * 16;
    const uint32_t boff = BH_ + (uint32_t)(wn * 64 + ((lane >> 4) & 1) * 8 + (lane & 7)) * 80 +
                          ((lane >> 3) & 1) * 16;

    {
        cpa16(sb + aD, aS);
        cpa16(sb + aD + 16, aS + 8);
#pragma unroll
        for (int j = 0; j < 4; j++) cpa16(sb + bD + j * 16, bS + j * 8);
        cpa_commit();
    }

    for (int c = 0; c < NC; c++) {
        cpa_wait0();
        __syncthreads();
        if (c + 1 < NC) {
            uint32_t st = sb + ((c + 1) & 1) * STG;
            const __half* ap = aS + (c + 1) * 32;
            const __half* bp = bS + (c + 1) * 32;
            cpa16(st + aD, ap);
            cpa16(st + aD + 16, ap + 8);
#pragma unroll
            for (int j = 0; j < 4; j++) cpa16(st + bD + j * 16, bp + j * 8);
            cpa_commit();
        }
        uint32_t st = sb + (c & 1) * STG;
#pragma unroll
        for (int kk = 0; kk < 2; kk++) {
            const uint32_t ko = kk * 32;
            uint32_t af[2][4], bf[8][2];
#pragma unroll
            for (int mi = 0; mi < 2; mi++) LDSM4(af[mi], st + aoff + mi * 1280 + ko);
#pragma unroll
            for (int p = 0; p < 4; p++) {
                uint32_t r4[4];
                LDSM4(r4, st + boff + p * 1280 + ko);
                bf[2 * p][0] = r4[0]; bf[2 * p][1] = r4[1];
                bf[2 * p + 1][0] = r4[2]; bf[2 * p + 1][1] = r4[3];
            }
#pragma unroll
            for (int mi = 0; mi < 2; mi++)
#pragma unroll
                for (int ni = 0; ni < 8; ni++) MMA16816(acc[mi][ni], af[mi], bf[ni]);
#pragma unroll
            for (int p = 0; p < 4; p++) {
                uint32_t r4[4];
                LDSM4(r4, st + boff + (BL_ - BH_) + p * 1280 + ko);
                bf[2 * p][0] = r4[0]; bf[2 * p][1] = r4[1];
                bf[2 * p + 1][0] = r4[2]; bf[2 * p + 1][1] = r4[3];
            }
#pragma unroll
            for (int mi = 0; mi < 2; mi++)
#pragma unroll
                for (int ni = 0; ni < 8; ni++) MMA16816(acc[mi][ni], af[mi], bf[ni]);
        }
        __syncthreads();
    }

    // epilogue (buffers NP-padded: no row guards)
    const int g = lane >> 2, q = lane & 3;
#pragma unroll
    for (int mi = 0; mi < 2; mi++)
#pragma unroll
        for (int ni = 0; ni < 8; ni++) {
            int r0 = m0 + wm * 32 + mi * 16 + g;
            int cc = colOff + nblk + wn * 64 + ni * 8 + 2 * q;
            float v0 = acc[mi][ni][0], v1 = acc[mi][ni][1];
            float v2 = acc[mi][ni][2], v3 = acc[mi][ni][3];
            if (EPI >= 1) {
                if (EPI == 1) {
                    v0 = fmaxf(v0, 0.f); v1 = fmaxf(v1, 0.f);
                    v2 = fmaxf(v2, 0.f); v3 = fmaxf(v3, 0.f);
                }
                __half2 a = __floats2half2_rn(v0, v1);
                __half2 b = __floats2half2_rn(v2, v3);
                *(__half2*)(Ch + (size_t)r0 * ldC + cc) = a;
                *(__half2*)(Ch + (size_t)(r0 + 8) * ldC + cc) = b;
            } else {
                *(float2*)(C + (size_t)r0 * ldC + cc) = make_float2(v0, v1);
                *(float2*)(C + (size_t)(r0 + 8) * ldC + cc) = make_float2(v2, v3);
            }
        }
}

// ---------------- LayerNorm + ReLU on f1, write fp16 into cat cols [256,512) ----------------
__global__ void k_ln(const float* __restrict__ gamma, const float* __restrict__ beta) {
    int warp = (blockIdx.x * blockDim.x + threadIdx.x) >> 5;
    int lane = threadIdx.x & 31;
    if (warp >= NP) return;
    const float* row = g_f1 + (size_t)warp * H4;
    float4 v0 = ((const float4*)row)[lane];
    float4 v1 = ((const float4*)row)[lane + 32];
    float s = v0.x + v0.y + v0.z + v0.w + v1.x + v1.y + v1.z + v1.w;
    float ss = v0.x * v0.x + v0.y * v0.y + v0.z * v0.z + v0.w * v0.w +
               v1.x * v1.x + v1.y * v1.y + v1.z * v1.z + v1.w * v1.w;
#pragma unroll
    for (int o = 16; o > 0; o >>= 1) {
        s += __shfl_xor_sync(0xffffffffu, s, o);
        ss += __shfl_xor_sync(0xffffffffu, ss, o);
    }
    float mean = s * (1.f / 256.f);
    float var = ss * (1.f / 256.f) - mean * mean;
    float rstd = rsqrtf(var + 1e-5f);
    float4 g0 = ((const float4*)gamma)[lane], g1 = ((const float4*)gamma)[lane + 32];
    float4 b0 = ((const float4*)beta)[lane], b1 = ((const float4*)beta)[lane + 32];
    v0.x = fmaxf((v0.x - mean) * rstd * g0.x + b0.x, 0.f);
    v0.y = fmaxf((v0.y - mean) * rstd * g0.y + b0.y, 0.f);
    v0.z = fmaxf((v0.z - mean) * rstd * g0.z + b0.z, 0.f);
    v0.w = fmaxf((v0.w - mean) * rstd * g0.w + b0.w, 0.f);
    v1.x = fmaxf((v1.x - mean) * rstd * g1.x + b1.x, 0.f);
    v1.y = fmaxf((v1.y - mean) * rstd * g1.y + b1.y, 0.f);
    v1.z = fmaxf((v1.z - mean) * rstd * g1.z + b1.z, 0.f);
    v1.w = fmaxf((v1.w - mean) * rstd * g1.w + b1.w, 0.f);
    uint32_t* ph = (uint32_t*)(g_c + (size_t)warp * CAT + H4);
    __half2 a = __floats2half2_rn(v0.x, v0.y), b = __floats2half2_rn(v0.z, v0.w);
    ph[lane * 2] = *(uint32_t*)&a;
    ph[lane * 2 + 1] = *(uint32_t*)&b;
    a = __floats2half2_rn(v1.x, v1.y); b = __floats2half2_rn(v1.z, v1.w);
    ph[64 + lane * 2] = *(uint32_t*)&a;
    ph[64 + lane * 2 + 1] = *(uint32_t*)&b;
}

// ---------------- readout normalize ----------------
__global__ void k_norm(float* __restrict__ out) {
    int b = blockIdx.x;
    int t = threadIdx.x;  // 128 threads
    float v = g_readout[b * OUTD + t];
    float ss = v * v;
#pragma unroll
    for (int o = 16; o > 0; o >>= 1) ss += __shfl_xor_sync(0xffffffffu, ss, o);
    __shared__ float sw[4];
    if ((t & 31) == 0) sw[t >> 5] = ss;
    __syncthreads();
    float tot = sw[0] + sw[1] + sw[2] + sw[3];
    float norm = fmaxf(sqrtf(tot), 1e-12f);
    out[b * OUTD + t] = v / norm;
}

// ---------------- launch ----------------
extern "C" void kernel_launch(void* const* d_in, const int* in_sizes, int n_in,
                              void* d_out, int out_size) {
    const float* x    = (const float*)d_in[0];
    const float* w    = (const float*)d_in[1];
    const float* W1   = (const float*)d_in[2];
    const float* fc1W = (const float*)d_in[3];
    const float* gam  = (const float*)d_in[4];
    const float* bet  = (const float*)d_in[5];
    const float* W2   = (const float*)d_in[6];
    const float* W3   = (const float*)d_in[7];
    const int*   src  = (const int*)d_in[8];
    const int*   dst  = (const int*)d_in[9];
    const int*   gid  = (const int*)d_in[10];
    float* out = (float*)d_out;

    float* p_f1;
    __half *p_bh, *p_bl, *p_xh, *p_a1, *p_c, *p_y2, *p_x2, *p_y3;
    cudaGetSymbolAddress((void**)&p_f1, g_f1);
    cudaGetSymbolAddress((void**)&p_bh, g_bh);
    cudaGetSymbolAddress((void**)&p_bl, g_bl);
    cudaGetSymbolAddress((void**)&p_xh, g_xh);
    cudaGetSymbolAddress((void**)&p_a1, g_a1);
    cudaGetSymbolAddress((void**)&p_c, g_c);
    cudaGetSymbolAddress((void**)&p_y2, g_y2);
    cudaGetSymbolAddress((void**)&p_x2, g_x2);
    cudaGetSymbolAddress((void**)&p_y3, g_y3);

    const int SMEM = 61440;
    cudaFuncSetAttribute(k_mma<128, 1>, cudaFuncAttributeMaxDynamicSharedMemorySize, SMEM);
    cudaFuncSetAttribute(k_mma<128, 0>, cudaFuncAttributeMaxDynamicSharedMemorySize, SMEM);
    cudaFuncSetAttribute(k_mma<512, 2>, cudaFuncAttributeMaxDynamicSharedMemorySize, SMEM);
    cudaFuncSetAttribute(k_mma<256, 2>, cudaFuncAttributeMaxDynamicSharedMemorySize, SMEM);

    const int TB = 256;
    // graph preprocessing
    k_zero<<<(NN + TB - 1) / TB, TB>>>();
    k_deg<<<(NE + TB - 1) / TB, TB>>>(src, dst);
    k_scan_a<<<40, 1024>>>();
    k_scan_c<<<40, 1024>>>();
    k_place<<<(NE + TB - 1) / TB, TB>>>(src, dst, w);
    // weight + x conversion (single kernel)
    k_conv_all<<<(WTOT + NP * IND + TB - 1) / TB, TB>>>(W1, fc1W, W2, W3, x);

    const int AGG_BLK = (NP * 32 + TB - 1) / TB;
    const int GX = NP / 128;  // 313

    // layer 1: agg(x_fp16) -> fp16 plane, GEMM 128->256 relu+fp16 into cat[:,0:256)
    k_agg<IND, 0><<<AGG_BLK, TB>>>(p_xh, p_a1, nullptr);
    k_mma<128, 1><<<dim3(GX, 2), TB, SMEM>>>(p_a1, p_bh + 0, p_bl + 0,
                                             nullptr, p_c, CAT, 0);
    // fc1: GEMM raw fp32 -> f1, then LN+relu+fp16 into cat[:,256:512)
    k_mma<128, 0><<<dim3(GX, 2), TB, SMEM>>>(p_xh, p_bh + 32768, p_bl + 32768,
                                             p_f1, nullptr, H4, 0);
    k_ln<<<AGG_BLK, TB>>>(gam, bet);
    // layer 2: GEMM 512->256 raw fp16, agg(fp16) + relu -> fp16 plane
    k_mma<512, 2><<<dim3(GX, 2), TB, SMEM>>>(p_c, p_bh + 65536, p_bl + 65536,
                                             nullptr, p_y2, H4, 0);
    k_agg<H4, 1><<<AGG_BLK, TB>>>(p_y2, p_x2, nullptr);
    // layer 3: GEMM 256->128 raw fp16, agg(fp16) + relu + readout
    k_mma<256, 2><<<dim3(GX, 1), TB, SMEM>>>(p_x2, p_bh + 196608, p_bl + 196608,
                                             nullptr, p_y3, OUTD, 0);
    k_agg<OUTD, 2><<<AGG_BLK, TB>>>(p_y3, nullptr, gid);
    // final L2 normalize
    k_norm<<<NG, OUTD>>>(out);
}

// round 8
// speedup vs baseline: 1.1205x; 1.1205x over previous
#include <cuda_runtime.h>
#include <cuda_fp16.h>
#include <cstdint>

#define NN 40000
#define NP 40064   // 313 * 128, padded row count
#define NE 320000
#define NG 64
#define IND 128
#define H4 256
#define OUTD 128
#define CAT 512

// ---------------- scratch (device globals; no allocation allowed) ----------------
__device__ int   g_outcnt[NN];
__device__ int   g_incnt[NN];
__device__ int   g_cursor[NN];
__device__ int   g_rowptr[NN + 1];
__device__ int   g_bsum[64];
__device__ float g_outinv[NN];
__device__ float g_ininv[NN];
__device__ int   g_es[NE];
__device__ float g_ec[NE];
__device__ float g_f1[NP * H4];
__device__ float g_readout[NG * OUTD];
// fp16 activations (padded to NP rows)
__device__ __half g_xh[NP * IND];    // x as fp16
__device__ __half g_a1[NP * IND];    // agg1
__device__ __half g_c[NP * CAT];     // concat [x1 | f1]
__device__ __half g_y2[NP * H4];     // layer2 GEMM out (pre-agg)
__device__ __half g_x2[NP * H4];     // x2
__device__ __half g_y3[NP * OUTD];   // layer3 GEMM out (pre-agg)
// weights fp16, transposed to [N][K]
// layout: W1 @0 (32768), fc1 @32768 (32768), W2 @65536 (131072), W3 @196608 (32768)
__device__ __half g_bh[229376];

// ---------------- helpers ----------------
__device__ __forceinline__ uint32_t smem_u32(const void* p) {
    uint32_t a;
    asm("{ .reg .u64 t; cvta.to.shared.u64 t, %1; cvt.u32.u64 %0, t; }" : "=r"(a) : "l"(p));
    return a;
}
__device__ __forceinline__ void cpa16(uint32_t dst, const void* src) {
    asm volatile("cp.async.cg.shared.global [%0], [%1], 16;" :: "r"(dst), "l"(src) : "memory");
}
__device__ __forceinline__ void cpa_commit() {
    asm volatile("cp.async.commit_group;" ::: "memory");
}
__device__ __forceinline__ void cpa_wait0() {
    asm volatile("cp.async.wait_group 0;" ::: "memory");
}
#define MMA16816(d, a, b)                                                     \
    asm volatile(                                                             \
        "mma.sync.aligned.m16n8k16.row.col.f32.f16.f16.f32 "                  \
        "{%0,%1,%2,%3}, {%4,%5,%6,%7}, {%8,%9}, {%0,%1,%2,%3};"               \
        : "+f"((d)[0]), "+f"((d)[1]), "+f"((d)[2]), "+f"((d)[3])              \
        : "r"((a)[0]), "r"((a)[1]), "r"((a)[2]), "r"((a)[3]),                 \
          "r"((b)[0]), "r"((b)[1]))
#define LDSM4(R, addr)                                                        \
    asm volatile("ldmatrix.sync.aligned.m8n8.x4.shared.b16 {%0,%1,%2,%3}, [%4];" \
        : "=r"((R)[0]), "=r"((R)[1]), "=r"((R)[2]), "=r"((R)[3]) : "r"(addr))

// ---------------- setup kernels ----------------
__global__ void k_zero() {
    int i = blockIdx.x * blockDim.x + threadIdx.x;
    if (i < NN) { g_outcnt[i] = 0; g_incnt[i] = 0; g_cursor[i] = 0; }
    if (i < NG * OUTD) g_readout[i] = 0.f;
}

__global__ void k_deg(const int* __restrict__ src, const int* __restrict__ dst) {
    int e = blockIdx.x * blockDim.x + threadIdx.x;
    if (e < NE) {
        atomicAdd(&g_outcnt[src[e]], 1);
        atomicAdd(&g_incnt[dst[e]], 1);
    }
}

// per-block scan (+ merged inv computation)
__global__ void k_scan_a() {
    __shared__ int sh[1024];
    int b = blockIdx.x, t = threadIdx.x;
    int idx = b * 1024 + t;
    int v = (idx < NN) ? g_incnt[idx] : 0;
    if (idx < NN) {
        g_ininv[idx]  = rsqrtf((float)max(v, 1));
        g_outinv[idx] = rsqrtf((float)max(g_outcnt[idx], 1));
    }
    sh[t] = v;
    __syncthreads();
#pragma unroll
    for (int off = 1; off < 1024; off <<= 1) {
        int u = (t >= off) ? sh[t - off] : 0;
        __syncthreads();
        sh[t] += u;
        __syncthreads();
    }
    int incl = sh[t];
    if (idx <= NN) g_rowptr[idx] = incl - v;
    if (t == 1023) g_bsum[b] = incl;
}
// add block-prefix offsets (parallel bsum staging, tiny serial add in shared)
__global__ void k_scan_c() {
    __shared__ int sbs[40];
    __shared__ int pre;
    int b = blockIdx.x, t = threadIdx.x;
    if (t < 40) sbs[t] = g_bsum[t];
    __syncthreads();
    if (t == 0) {
        int s = 0;
        for (int i = 0; i < b; i++) s += sbs[i];
        pre = s;
    }
    __syncthreads();
    int idx = b * 1024 + t;
    if (idx <= NN) g_rowptr[idx] += pre;
}

__global__ void k_place(const int* __restrict__ src, const int* __restrict__ dst,
                        const float* __restrict__ w) {
    int e = blockIdx.x * blockDim.x + threadIdx.x;
    if (e >= NE) return;
    float4 ww = *(const float4*)(w + 4 * e);
    float m = fmaxf(fmaxf(ww.x, ww.y), fmaxf(ww.z, ww.w));
    int d = dst[e];
    int s = src[e];
    int pos = g_rowptr[d] + atomicAdd(&g_cursor[d], 1);
    g_es[pos] = s;
    g_ec[pos] = m * g_outinv[s];
}

// weights fp32 [K][N] -> fp16 [N][K]  AND  x -> fp16 plane, one kernel
#define WTOT 229376
__global__ void k_conv_all(const float* __restrict__ W1, const float* __restrict__ F1,
                           const float* __restrict__ W2, const float* __restrict__ W3,
                           const float* __restrict__ x) {
    int idx = blockIdx.x * blockDim.x + threadIdx.x;
    if (idx < WTOT) {
        const float* W; int K, N, base;
        if (idx < 32768)       { W = W1; K = 128; N = 256; base = 0; }
        else if (idx < 65536)  { W = F1; K = 128; N = 256; base = 32768; }
        else if (idx < 196608) { W = W2; K = 512; N = 256; base = 65536; }
        else                   { W = W3; K = 256; N = 128; base = 196608; }
        int li = idx - base;
        int k = li % K, n = li / K;
        g_bh[idx] = __float2half_rn(W[k * N + n]);
    } else {
        int j = idx - WTOT;
        if (j < NP * IND) {
            float v = (j < NN * IND) ? x[j] : 0.f;
            g_xh[j] = __float2half_rn(v);
        }
    }
}

// ---------------- aggregation: one warp per dst node, fp16 gather ----------------
// MODE 0: fp16 out (no relu); MODE 1: relu + fp16 out; MODE 2: relu + readout atomics
template <int D, int MODE>
__global__ void k_agg(const __half* __restrict__ in, __half* __restrict__ oh,
                      const int* __restrict__ gid) {
    int warp = (blockIdx.x * blockDim.x + threadIdx.x) >> 5;
    int lane = threadIdx.x & 31;
    if (warp >= NP) return;
    constexpr int V = D / 64;  // half2 units per lane
    if (warp >= NN) {  // pad rows: zero plane
        if (MODE != 2) {
            uint32_t* ph = (uint32_t*)(oh + (size_t)warp * D);
#pragma unroll
            for (int v = 0; v < V; v++) ph[lane * V + v] = 0;
        }
        return;
    }
    int beg = g_rowptr[warp];
    int end = g_rowptr[warp + 1];
    float2 acc[V];
#pragma unroll
    for (int v = 0; v < V; v++) acc[v] = make_float2(0.f, 0.f);
    int e = beg;
    for (; e + 1 < end; e += 2) {
        int s0 = g_es[e], s1 = g_es[e + 1];
        float c0 = g_ec[e], c1 = g_ec[e + 1];
        const uint32_t* p0 = (const uint32_t*)(in + (size_t)s0 * D) + lane * V;
        const uint32_t* p1 = (const uint32_t*)(in + (size_t)s1 * D) + lane * V;
        uint32_t t0[V], t1[V];
#pragma unroll
        for (int v = 0; v < V; v++) { t0[v] = p0[v]; t1[v] = p1[v]; }
#pragma unroll
        for (int v = 0; v < V; v++) {
            float2 f0 = __half22float2(*(const __half2*)&t0[v]);
            float2 f1 = __half22float2(*(const __half2*)&t1[v]);
            acc[v].x = fmaf(c0, f0.x, fmaf(c1, f1.x, acc[v].x));
            acc[v].y = fmaf(c0, f0.y, fmaf(c1, f1.y, acc[v].y));
        }
    }
    if (e < end) {
        int s = g_es[e];
        float c = g_ec[e];
        const uint32_t* p = (const uint32_t*)(in + (size_t)s * D) + lane * V;
#pragma unroll
        for (int v = 0; v < V; v++) {
            uint32_t t = p[v];
            float2 f = __half22float2(*(const __half2*)&t);
            acc[v].x = fmaf(c, f.x, acc[v].x);
            acc[v].y = fmaf(c, f.y, acc[v].y);
        }
    }
    float inv = g_ininv[warp];
#pragma unroll
    for (int v = 0; v < V; v++) {
        acc[v].x *= inv; acc[v].y *= inv;
        if (MODE >= 1) {
            acc[v].x = fmaxf(acc[v].x, 0.f);
            acc[v].y = fmaxf(acc[v].y, 0.f);
        }
    }
    if (MODE == 2) {
        int g = gid[warp];
        float* r = g_readout + g * OUTD + lane * 4;
        atomicAdd(r + 0, acc[0].x);
        atomicAdd(r + 1, acc[0].y);
        atomicAdd(r + 2, acc[1].x);
        atomicAdd(r + 3, acc[1].y);
    } else {
        uint32_t* ph = (uint32_t*)(oh + (size_t)warp * D);
#pragma unroll
        for (int v = 0; v < V; v++) {
            __half2 a = __floats2half2_rn(acc[v].x, acc[v].y);
            ph[lane * V + v] = *(uint32_t*)&a;
        }
    }
}

// ---------------- fp16 single-pass mma.sync GEMM ----------------
// C[M,N] = A@B, both fp16, fp32 accum.
// Block tile 128x128, BK=32 per stage, 2-stage cp.async pipeline, 80B-padded smem rows.
// EPI: 0 = raw fp32 out, 1 = relu + fp16 out, 2 = raw fp16 out
template <int K, int EPI>
__global__ __launch_bounds__(256, 2) void k_mma(
    const __half* __restrict__ Ah, const __half* __restrict__ Bh,
    float* __restrict__ C, __half* __restrict__ Ch, int ldC, int colOff) {
    extern __shared__ __align__(16) uint8_t smem[];
    constexpr int NC = K / 32;
    constexpr uint32_t AH_ = 0, BH_ = 10240, STG = 20480;
    const int tid = threadIdx.x;
    const int wid = tid >> 5, lane = tid & 31;
    const int wm = wid & 3, wn = wid >> 2;
    const int m0 = blockIdx.x * 128;
    const int nblk = blockIdx.y * 128;
    const uint32_t sb = smem_u32(smem);

    float acc[2][8][4];
#pragma unroll
    for (int mi = 0; mi < 2; mi++)
#pragma unroll
        for (int ni = 0; ni < 8; ni++)
#pragma unroll
            for (int r = 0; r < 4; r++) acc[mi][ni][r] = 0.f;

    // loader: tid<128 -> A row, tid>=128 -> B row; 64B (one BK) per thread per stage
    const int lrow = tid & 127;
    const bool isB = tid >= 128;
    const __half* gS = isB ? (Bh + (size_t)(nblk + lrow) * K)
                           : (Ah + (size_t)(m0 + lrow) * K);
    const uint32_t gD = (isB ? BH_ : AH_) + (uint32_t)lrow * 80;

    // fragment base offsets (ldmatrix thread mapping)
    const uint32_t aoff = AH_ + (uint32_t)(wm * 32 + (lane & 7) + ((lane >> 3) & 1) * 8) * 80 +
                          (lane >> 4) * 16;
    const uint32_t boff = BH_ + (uint32_t)(wn * 64 + ((lane >> 4) & 1) * 8 + (lane & 7)) * 80 +
                          ((lane >> 3) & 1) * 16;

    {
#pragma unroll
        for (int j = 0; j < 4; j++) cpa16(sb + gD + j * 16, gS + j * 8);
        cpa_commit();
    }

    for (int c = 0; c < NC; c++) {
        cpa_wait0();
        __syncthreads();
        if (c + 1 < NC) {
            uint32_t st = sb + ((c + 1) & 1) * STG;
            const __half* gp = gS + (c + 1) * 32;
#pragma unroll
            for (int j = 0; j < 4; j++) cpa16(st + gD + j * 16, gp + j * 8);
            cpa_commit();
        }
        uint32_t st = sb + (c & 1) * STG;
#pragma unroll
        for (int kk = 0; kk < 2; kk++) {
            const uint32_t ko = kk * 32;
            uint32_t af[2][4], bf[8][2];
#pragma unroll
            for (int mi = 0; mi < 2; mi++) LDSM4(af[mi], st + aoff + mi * 1280 + ko);
#pragma unroll
            for (int p = 0; p < 4; p++) {
                uint32_t r4[4];
                LDSM4(r4, st + boff + p * 1280 + ko);
                bf[2 * p][0] = r4[0]; bf[2 * p][1] = r4[1];
                bf[2 * p + 1][0] = r4[2]; bf[2 * p + 1][1] = r4[3];
            }
#pragma unroll
            for (int mi = 0; mi < 2; mi++)
#pragma unroll
                for (int ni = 0; ni < 8; ni++) MMA16816(acc[mi][ni], af[mi], bf[ni]);
        }
        __syncthreads();
    }

    // epilogue (buffers NP-padded: no row guards)
    const int g = lane >> 2, q = lane & 3;
#pragma unroll
    for (int mi = 0; mi < 2; mi++)
#pragma unroll
        for (int ni = 0; ni < 8; ni++) {
            int r0 = m0 + wm * 32 + mi * 16 + g;
            int cc = colOff + nblk + wn * 64 + ni * 8 + 2 * q;
            float v0 = acc[mi][ni][0], v1 = acc[mi][ni][1];
            float v2 = acc[mi][ni][2], v3 = acc[mi][ni][3];
            if (EPI >= 1) {
                if (EPI == 1) {
                    v0 = fmaxf(v0, 0.f); v1 = fmaxf(v1, 0.f);
                    v2 = fmaxf(v2, 0.f); v3 = fmaxf(v3, 0.f);
                }
                __half2 a = __floats2half2_rn(v0, v1);
                __half2 b = __floats2half2_rn(v2, v3);
                *(__half2*)(Ch + (size_t)r0 * ldC + cc) = a;
                *(__half2*)(Ch + (size_t)(r0 + 8) * ldC + cc) = b;
            } else {
                *(float2*)(C + (size_t)r0 * ldC + cc) = make_float2(v0, v1);
                *(float2*)(C + (size_t)(r0 + 8) * ldC + cc) = make_float2(v2, v3);
            }
        }
}

// ---------------- LayerNorm + ReLU on f1, write fp16 into cat cols [256,512) ----------------
__global__ void k_ln(const float* __restrict__ gamma, const float* __restrict__ beta) {
    int warp = (blockIdx.x * blockDim.x + threadIdx.x) >> 5;
    int lane = threadIdx.x & 31;
    if (warp >= NP) return;
    const float* row = g_f1 + (size_t)warp * H4;
    float4 v0 = ((const float4*)row)[lane];
    float4 v1 = ((const float4*)row)[lane + 32];
    float s = v0.x + v0.y + v0.z + v0.w + v1.x + v1.y + v1.z + v1.w;
    float ss = v0.x * v0.x + v0.y * v0.y + v0.z * v0.z + v0.w * v0.w +
               v1.x * v1.x + v1.y * v1.y + v1.z * v1.z + v1.w * v1.w;
#pragma unroll
    for (int o = 16; o > 0; o >>= 1) {
        s += __shfl_xor_sync(0xffffffffu, s, o);
        ss += __shfl_xor_sync(0xffffffffu, ss, o);
    }
    float mean = s * (1.f / 256.f);
    float var = ss * (1.f / 256.f) - mean * mean;
    float rstd = rsqrtf(var + 1e-5f);
    float4 g0 = ((const float4*)gamma)[lane], g1 = ((const float4*)gamma)[lane + 32];
    float4 b0 = ((const float4*)beta)[lane], b1 = ((const float4*)beta)[lane + 32];
    v0.x = fmaxf((v0.x - mean) * rstd * g0.x + b0.x, 0.f);
    v0.y = fmaxf((v0.y - mean) * rstd * g0.y + b0.y, 0.f);
    v0.z = fmaxf((v0.z - mean) * rstd * g0.z + b0.z, 0.f);
    v0.w = fmaxf((v0.w - mean) * rstd * g0.w + b0.w, 0.f);
    v1.x = fmaxf((v1.x - mean) * rstd * g1.x + b1.x, 0.f);
    v1.y = fmaxf((v1.y - mean) * rstd * g1.y + b1.y, 0.f);
    v1.z = fmaxf((v1.z - mean) * rstd * g1.z + b1.z, 0.f);
    v1.w = fmaxf((v1.w - mean) * rstd * g1.w + b1.w, 0.f);
    uint32_t* ph = (uint32_t*)(g_c + (size_t)warp * CAT + H4);
    __half2 a = __floats2half2_rn(v0.x, v0.y), b = __floats2half2_rn(v0.z, v0.w);
    ph[lane * 2] = *(uint32_t*)&a;
    ph[lane * 2 + 1] = *(uint32_t*)&b;
    a = __floats2half2_rn(v1.x, v1.y); b = __floats2half2_rn(v1.z, v1.w);
    ph[64 + lane * 2] = *(uint32_t*)&a;
    ph[64 + lane * 2 + 1] = *(uint32_t*)&b;
}

// ---------------- readout normalize ----------------
__global__ void k_norm(float* __restrict__ out) {
    int b = blockIdx.x;
    int t = threadIdx.x;  // 128 threads
    float v = g_readout[b * OUTD + t];
    float ss = v * v;
#pragma unroll
    for (int o = 16; o > 0; o >>= 1) ss += __shfl_xor_sync(0xffffffffu, ss, o);
    __shared__ float sw[4];
    if ((t & 31) == 0) sw[t >> 5] = ss;
    __syncthreads();
    float tot = sw[0] + sw[1] + sw[2] + sw[3];
    float norm = fmaxf(sqrtf(tot), 1e-12f);
    out[b * OUTD + t] = v / norm;
}

// ---------------- launch ----------------
extern "C" void kernel_launch(void* const* d_in, const int* in_sizes, int n_in,
                              void* d_out, int out_size) {
    const float* x    = (const float*)d_in[0];
    const float* w    = (const float*)d_in[1];
    const float* W1   = (const float*)d_in[2];
    const float* fc1W = (const float*)d_in[3];
    const float* gam  = (const float*)d_in[4];
    const float* bet  = (const float*)d_in[5];
    const float* W2   = (const float*)d_in[6];
    const float* W3   = (const float*)d_in[7];
    const int*   src  = (const int*)d_in[8];
    const int*   dst  = (const int*)d_in[9];
    const int*   gid  = (const int*)d_in[10];
    float* out = (float*)d_out;

    float* p_f1;
    __half *p_bh, *p_xh, *p_a1, *p_c, *p_y2, *p_x2, *p_y3;
    cudaGetSymbolAddress((void**)&p_f1, g_f1);
    cudaGetSymbolAddress((void**)&p_bh, g_bh);
    cudaGetSymbolAddress((void**)&p_xh, g_xh);
    cudaGetSymbolAddress((void**)&p_a1, g_a1);
    cudaGetSymbolAddress((void**)&p_c, g_c);
    cudaGetSymbolAddress((void**)&p_y2, g_y2);
    cudaGetSymbolAddress((void**)&p_x2, g_x2);
    cudaGetSymbolAddress((void**)&p_y3, g_y3);

    const int SMEM = 40960;
    cudaFuncSetAttribute(k_mma<128, 1>, cudaFuncAttributeMaxDynamicSharedMemorySize, SMEM);
    cudaFuncSetAttribute(k_mma<128, 0>, cudaFuncAttributeMaxDynamicSharedMemorySize, SMEM);
    cudaFuncSetAttribute(k_mma<512, 2>, cudaFuncAttributeMaxDynamicSharedMemorySize, SMEM);
    cudaFuncSetAttribute(k_mma<256, 2>, cudaFuncAttributeMaxDynamicSharedMemorySize, SMEM);

    const int TB = 256;
    // graph preprocessing
    k_zero<<<(NN + TB - 1) / TB, TB>>>();
    k_deg<<<(NE + TB - 1) / TB, TB>>>(src, dst);
    k_scan_a<<<40, 1024>>>();
    k_scan_c<<<40, 1024>>>();
    k_place<<<(NE + TB - 1) / TB, TB>>>(src, dst, w);
    // weight + x conversion (single kernel)
    k_conv_all<<<(WTOT + NP * IND + TB - 1) / TB, TB>>>(W1, fc1W, W2, W3, x);

    const int AGG_BLK = (NP * 32 + TB - 1) / TB;
    const int GX = NP / 128;  // 313

    // layer 1: agg(x_fp16) -> fp16 plane, GEMM 128->256 relu+fp16 into cat[:,0:256)
    k_agg<IND, 0><<<AGG_BLK, TB>>>(p_xh, p_a1, nullptr);
    k_mma<128, 1><<<dim3(GX, 2), TB, SMEM>>>(p_a1, p_bh + 0, nullptr, p_c, CAT, 0);
    // fc1: GEMM raw fp32 -> f1, then LN+relu+fp16 into cat[:,256:512)
    k_mma<128, 0><<<dim3(GX, 2), TB, SMEM>>>(p_xh, p_bh + 32768, p_f1, nullptr, H4, 0);
    k_ln<<<AGG_BLK, TB>>>(gam, bet);
    // layer 2: GEMM 512->256 raw fp16, agg(fp16) + relu -> fp16 plane
    k_mma<512, 2><<<dim3(GX, 2), TB, SMEM>>>(p_c, p_bh + 65536, nullptr, p_y2, H4, 0);
    k_agg<H4, 1><<<AGG_BLK, TB>>>(p_y2, p_x2, nullptr);
    // layer 3: GEMM 256->128 raw fp16, agg(fp16) + relu + readout
    k_mma<256, 2><<<dim3(GX, 1), TB, SMEM>>>(p_x2, p_bh + 196608, nullptr, p_y3, OUTD, 0);
    k_agg<OUTD, 2><<<AGG_BLK, TB>>>(p_y3, nullptr, gid);
    // final L2 normalize
    k_norm<<<NG, OUTD>>>(out);
}

// round 9
// speedup vs baseline: 1.1555x; 1.0312x over previous
#include <cuda_runtime.h>
#include <cuda_fp16.h>
#include <cstdint>

#define NN 40000
#define NP 40064   // 313 * 128, padded row count
#define NE 320000
#define NG 64
#define IND 128
#define H4 256
#define OUTD 128
#define CAT 512

// ---------------- scratch (device globals; no allocation allowed) ----------------
__device__ int   g_outcnt[NN];
__device__ int   g_incnt[NN];
__device__ int   g_cursor[NN];
__device__ int   g_rowptr[NN + 1];
__device__ int   g_bsum[64];
__device__ float g_outinv[NN];
__device__ float g_ininv[NN];
__device__ int   g_es[NE];
__device__ float g_ec[NE];
__device__ float g_readout[NG * OUTD];
// fp16 activations (padded to NP rows)
__device__ __half g_xh[NP * IND];    // x as fp16
__device__ __half g_a1[NP * IND];    // agg1
__device__ __half g_c[NP * CAT];     // concat [x1 | f1]
__device__ __half g_f1h[NP * H4];    // fc1 raw out (pre-LN), fp16
__device__ __half g_y2[NP * H4];     // layer2 GEMM out (pre-agg)
__device__ __half g_x2[NP * H4];     // x2
__device__ __half g_y3[NP * OUTD];   // layer3 GEMM out (pre-agg)
// weights fp16, transposed to [N][K]
// layout: W1 @0 (32768), fc1 @32768 (32768), W2 @65536 (131072), W3 @196608 (32768)
__device__ __half g_bh[229376];

// ---------------- helpers ----------------
__device__ __forceinline__ uint32_t smem_u32(const void* p) {
    uint32_t a;
    asm("{ .reg .u64 t; cvta.to.shared.u64 t, %1; cvt.u32.u64 %0, t; }" : "=r"(a) : "l"(p));
    return a;
}
__device__ __forceinline__ void cpa16(uint32_t dst, const void* src) {
    asm volatile("cp.async.cg.shared.global [%0], [%1], 16;" :: "r"(dst), "l"(src) : "memory");
}
__device__ __forceinline__ void cpa_commit() {
    asm volatile("cp.async.commit_group;" ::: "memory");
}
#define MMA16816(d, a, b)                                                     \
    asm volatile(                                                             \
        "mma.sync.aligned.m16n8k16.row.col.f32.f16.f16.f32 "                  \
        "{%0,%1,%2,%3}, {%4,%5,%6,%7}, {%8,%9}, {%0,%1,%2,%3};"               \
        : "+f"((d)[0]), "+f"((d)[1]), "+f"((d)[2]), "+f"((d)[3])              \
        : "r"((a)[0]), "r"((a)[1]), "r"((a)[2]), "r"((a)[3]),                 \
          "r"((b)[0]), "r"((b)[1]))
#define LDSM4(R, addr)                                                        \
    asm volatile("ldmatrix.sync.aligned.m8n8.x4.shared.b16 {%0,%1,%2,%3}, [%4];" \
        : "=r"((R)[0]), "=r"((R)[1]), "=r"((R)[2]), "=r"((R)[3]) : "r"(addr))

// ---------------- setup kernels ----------------
// merged: zero counters/readout + convert weights + convert x (all independent)
#define WTOT 229376
__global__ void k_zero_conv(const float* __restrict__ W1, const float* __restrict__ F1,
                            const float* __restrict__ W2, const float* __restrict__ W3,
                            const float* __restrict__ x) {
    int idx = blockIdx.x * blockDim.x + threadIdx.x;
    if (idx < NN) { g_outcnt[idx] = 0; g_incnt[idx] = 0; g_cursor[idx] = 0; }
    if (idx < NG * OUTD) g_readout[idx] = 0.f;
    if (idx < WTOT) {
        const float* W; int K, N, base;
        if (idx < 32768)       { W = W1; K = 128; N = 256; base = 0; }
        else if (idx < 65536)  { W = F1; K = 128; N = 256; base = 32768; }
        else if (idx < 196608) { W = W2; K = 512; N = 256; base = 65536; }
        else                   { W = W3; K = 256; N = 128; base = 196608; }
        int li = idx - base;
        int k = li % K, n = li / K;
        g_bh[idx] = __float2half_rn(W[k * N + n]);
    } else {
        int j = idx - WTOT;
        if (j < NP * IND) {
            float v = (j < NN * IND) ? x[j] : 0.f;
            g_xh[j] = __float2half_rn(v);
        }
    }
}

__global__ void k_deg(const int* __restrict__ src, const int* __restrict__ dst) {
    int e = blockIdx.x * blockDim.x + threadIdx.x;
    if (e < NE) {
        atomicAdd(&g_outcnt[src[e]], 1);
        atomicAdd(&g_incnt[dst[e]], 1);
    }
}

// per-block scan (+ merged inv computation)
__global__ void k_scan_a() {
    __shared__ int sh[1024];
    int b = blockIdx.x, t = threadIdx.x;
    int idx = b * 1024 + t;
    int v = (idx < NN) ? g_incnt[idx] : 0;
    if (idx < NN) {
        g_ininv[idx]  = rsqrtf((float)max(v, 1));
        g_outinv[idx] = rsqrtf((float)max(g_outcnt[idx], 1));
    }
    sh[t] = v;
    __syncthreads();
#pragma unroll
    for (int off = 1; off < 1024; off <<= 1) {
        int u = (t >= off) ? sh[t - off] : 0;
        __syncthreads();
        sh[t] += u;
        __syncthreads();
    }
    int incl = sh[t];
    if (idx <= NN) g_rowptr[idx] = incl - v;
    if (t == 1023) g_bsum[b] = incl;
}
// add block-prefix offsets
__global__ void k_scan_c() {
    __shared__ int sbs[40];
    __shared__ int pre;
    int b = blockIdx.x, t = threadIdx.x;
    if (t < 40) sbs[t] = g_bsum[t];
    __syncthreads();
    if (t == 0) {
        int s = 0;
        for (int i = 0; i < b; i++) s += sbs[i];
        pre = s;
    }
    __syncthreads();
    int idx = b * 1024 + t;
    if (idx <= NN) g_rowptr[idx] += pre;
}

__global__ void k_place(const int* __restrict__ src, const int* __restrict__ dst,
                        const float* __restrict__ w) {
    int e = blockIdx.x * blockDim.x + threadIdx.x;
    if (e >= NE) return;
    float4 ww = *(const float4*)(w + 4 * e);
    float m = fmaxf(fmaxf(ww.x, ww.y), fmaxf(ww.z, ww.w));
    int d = dst[e];
    int s = src[e];
    int pos = g_rowptr[d] + atomicAdd(&g_cursor[d], 1);
    g_es[pos] = s;
    g_ec[pos] = m * g_outinv[s];
}

// ---------------- aggregation: one warp per dst node, fp16 gather ----------------
// MODE 0: fp16 out (no relu); MODE 1: relu + fp16 out; MODE 2: relu + readout atomics
template <int D, int MODE>
__global__ void k_agg(const __half* __restrict__ in, __half* __restrict__ oh,
                      const int* __restrict__ gid) {
    int warp = (blockIdx.x * blockDim.x + threadIdx.x) >> 5;
    int lane = threadIdx.x & 31;
    if (warp >= NP) return;
    constexpr int V = D / 64;  // half2 units per lane
    if (warp >= NN) {  // pad rows: zero plane
        if (MODE != 2) {
            uint32_t* ph = (uint32_t*)(oh + (size_t)warp * D);
#pragma unroll
            for (int v = 0; v < V; v++) ph[lane * V + v] = 0;
        }
        return;
    }
    int beg = g_rowptr[warp];
    int end = g_rowptr[warp + 1];
    float2 acc[V];
#pragma unroll
    for (int v = 0; v < V; v++) acc[v] = make_float2(0.f, 0.f);
    int e = beg;
    for (; e + 1 < end; e += 2) {
        int s0 = g_es[e], s1 = g_es[e + 1];
        float c0 = g_ec[e], c1 = g_ec[e + 1];
        const uint32_t* p0 = (const uint32_t*)(in + (size_t)s0 * D) + lane * V;
        const uint32_t* p1 = (const uint32_t*)(in + (size_t)s1 * D) + lane * V;
        uint32_t t0[V], t1[V];
#pragma unroll
        for (int v = 0; v < V; v++) { t0[v] = p0[v]; t1[v] = p1[v]; }
#pragma unroll
        for (int v = 0; v < V; v++) {
            float2 f0 = __half22float2(*(const __half2*)&t0[v]);
            float2 f1 = __half22float2(*(const __half2*)&t1[v]);
            acc[v].x = fmaf(c0, f0.x, fmaf(c1, f1.x, acc[v].x));
            acc[v].y = fmaf(c0, f0.y, fmaf(c1, f1.y, acc[v].y));
        }
    }
    if (e < end) {
        int s = g_es[e];
        float c = g_ec[e];
        const uint32_t* p = (const uint32_t*)(in + (size_t)s * D) + lane * V;
#pragma unroll
        for (int v = 0; v < V; v++) {
            uint32_t t = p[v];
            float2 f = __half22float2(*(const __half2*)&t);
            acc[v].x = fmaf(c, f.x, acc[v].x);
            acc[v].y = fmaf(c, f.y, acc[v].y);
        }
    }
    float inv = g_ininv[warp];
#pragma unroll
    for (int v = 0; v < V; v++) {
        acc[v].x *= inv; acc[v].y *= inv;
        if (MODE >= 1) {
            acc[v].x = fmaxf(acc[v].x, 0.f);
            acc[v].y = fmaxf(acc[v].y, 0.f);
        }
    }
    if (MODE == 2) {
        int g = gid[warp];
        float* r = g_readout + g * OUTD + lane * 4;
        atomicAdd(r + 0, acc[0].x);
        atomicAdd(r + 1, acc[0].y);
        atomicAdd(r + 2, acc[1].x);
        atomicAdd(r + 3, acc[1].y);
    } else {
        uint32_t* ph = (uint32_t*)(oh + (size_t)warp * D);
#pragma unroll
        for (int v = 0; v < V; v++) {
            __half2 a = __floats2half2_rn(acc[v].x, acc[v].y);
            ph[lane * V + v] = *(uint32_t*)&a;
        }
    }
}

// ---------------- fp16 single-pass mma.sync GEMM, 3-stage pipeline ----------------
// C[M,N] = A@B, both fp16, fp32 accum. Block tile 128x128, BK=32/stage, 3 stages,
// one __syncthreads per chunk. 80B-padded smem rows. EPI: 1 = relu+fp16, 2 = raw fp16.
template <int K, int EPI>
__global__ __launch_bounds__(256, 2) void k_mma(
    const __half* __restrict__ Ah, const __half* __restrict__ Bh,
    __half* __restrict__ Ch, int ldC, int colOff) {
    extern __shared__ __align__(16) uint8_t smem[];
    constexpr int NC = K / 32;
    constexpr uint32_t AH_ = 0, BH_ = 10240, STG = 20480;
    const int tid = threadIdx.x;
    const int wid = tid >> 5, lane = tid & 31;
    const int wm = wid & 3, wn = wid >> 2;
    const int m0 = blockIdx.x * 128;
    const int nblk = blockIdx.y * 128;
    const uint32_t sb = smem_u32(smem);

    float acc[2][8][4];
#pragma unroll
    for (int mi = 0; mi < 2; mi++)
#pragma unroll
        for (int ni = 0; ni < 8; ni++)
#pragma unroll
            for (int r = 0; r < 4; r++) acc[mi][ni][r] = 0.f;

    // loader: tid<128 -> A row, tid>=128 -> B row; 64B (one BK) per thread per stage
    const int lrow = tid & 127;
    const bool isB = tid >= 128;
    const __half* gS = isB ? (Bh + (size_t)(nblk + lrow) * K)
                           : (Ah + (size_t)(m0 + lrow) * K);
    const uint32_t gD = (isB ? BH_ : AH_) + (uint32_t)lrow * 80;

    const uint32_t aoff = AH_ + (uint32_t)(wm * 32 + (lane & 7) + ((lane >> 3) & 1) * 8) * 80 +
                          (lane >> 4) * 16;
    const uint32_t boff = BH_ + (uint32_t)(wn * 64 + ((lane >> 4) & 1) * 8 + (lane & 7)) * 80 +
                          ((lane >> 3) & 1) * 16;

    // prologue: stages 0,1
    {
        uint32_t st = sb;
        const __half* gp = gS;
#pragma unroll
        for (int j = 0; j < 4; j++) cpa16(st + gD + j * 16, gp + j * 8);
        cpa_commit();
        st = sb + STG;
        gp = gS + 32;
#pragma unroll
        for (int j = 0; j < 4; j++) cpa16(st + gD + j * 16, gp + j * 8);
        cpa_commit();
    }

    for (int c = 0; c < NC; c++) {
        if (c + 1 < NC)
            asm volatile("cp.async.wait_group 1;" ::: "memory");
        else
            asm volatile("cp.async.wait_group 0;" ::: "memory");
        __syncthreads();
        if (c + 2 < NC) {
            uint32_t st = sb + ((c + 2) % 3) * STG;
            const __half* gp = gS + (c + 2) * 32;
#pragma unroll
            for (int j = 0; j < 4; j++) cpa16(st + gD + j * 16, gp + j * 8);
            cpa_commit();
        }
        uint32_t st = sb + (c % 3) * STG;
#pragma unroll
        for (int kk = 0; kk < 2; kk++) {
            const uint32_t ko = kk * 32;
            uint32_t af[2][4], bf[8][2];
#pragma unroll
            for (int mi = 0; mi < 2; mi++) LDSM4(af[mi], st + aoff + mi * 1280 + ko);
#pragma unroll
            for (int p = 0; p < 4; p++) {
                uint32_t r4[4];
                LDSM4(r4, st + boff + p * 1280 + ko);
                bf[2 * p][0] = r4[0]; bf[2 * p][1] = r4[1];
                bf[2 * p + 1][0] = r4[2]; bf[2 * p + 1][1] = r4[3];
            }
#pragma unroll
            for (int mi = 0; mi < 2; mi++)
#pragma unroll
                for (int ni = 0; ni < 8; ni++) MMA16816(acc[mi][ni], af[mi], bf[ni]);
        }
    }

    // epilogue (buffers NP-padded: no row guards); fp16 out always
    const int g = lane >> 2, q = lane & 3;
#pragma unroll
    for (int mi = 0; mi < 2; mi++)
#pragma unroll
        for (int ni = 0; ni < 8; ni++) {
            int r0 = m0 + wm * 32 + mi * 16 + g;
            int cc = colOff + nblk + wn * 64 + ni * 8 + 2 * q;
            float v0 = acc[mi][ni][0], v1 = acc[mi][ni][1];
            float v2 = acc[mi][ni][2], v3 = acc[mi][ni][3];
            if (EPI == 1) {
                v0 = fmaxf(v0, 0.f); v1 = fmaxf(v1, 0.f);
                v2 = fmaxf(v2, 0.f); v3 = fmaxf(v3, 0.f);
            }
            __half2 a = __floats2half2_rn(v0, v1);
            __half2 b = __floats2half2_rn(v2, v3);
            *(__half2*)(Ch + (size_t)r0 * ldC + cc) = a;
            *(__half2*)(Ch + (size_t)(r0 + 8) * ldC + cc) = b;
        }
}

// ---------------- LayerNorm + ReLU on fp16 f1, write fp16 into cat cols [256,512) ----------------
__global__ void k_ln(const float* __restrict__ gamma, const float* __restrict__ beta) {
    int warp = (blockIdx.x * blockDim.x + threadIdx.x) >> 5;
    int lane = threadIdx.x & 31;
    if (warp >= NP) return;
    const uint4* row = (const uint4*)(g_f1h + (size_t)warp * H4);
    uint4 u = row[lane];  // 8 halves per lane
    float f[8];
#pragma unroll
    for (int i = 0; i < 4; i++) {
        float2 p = __half22float2(*(const __half2*)(((const uint32_t*)&u) + i));
        f[2 * i] = p.x;
        f[2 * i + 1] = p.y;
    }
    float s = 0.f, ss = 0.f;
#pragma unroll
    for (int i = 0; i < 8; i++) { s += f[i]; ss += f[i] * f[i]; }
#pragma unroll
    for (int o = 16; o > 0; o >>= 1) {
        s += __shfl_xor_sync(0xffffffffu, s, o);
        ss += __shfl_xor_sync(0xffffffffu, ss, o);
    }
    float mean = s * (1.f / 256.f);
    float var = ss * (1.f / 256.f) - mean * mean;
    float rstd = rsqrtf(var + 1e-5f);
    float4 g0 = ((const float4*)gamma)[2 * lane], g1 = ((const float4*)gamma)[2 * lane + 1];
    float4 b0 = ((const float4*)beta)[2 * lane], b1 = ((const float4*)beta)[2 * lane + 1];
    float gv[8] = {g0.x, g0.y, g0.z, g0.w, g1.x, g1.y, g1.z, g1.w};
    float bv[8] = {b0.x, b0.y, b0.z, b0.w, b1.x, b1.y, b1.z, b1.w};
    uint32_t outw[4];
#pragma unroll
    for (int i = 0; i < 4; i++) {
        float v0 = fmaxf((f[2 * i] - mean) * rstd * gv[2 * i] + bv[2 * i], 0.f);
        float v1 = fmaxf((f[2 * i + 1] - mean) * rstd * gv[2 * i + 1] + bv[2 * i + 1], 0.f);
        __half2 h = __floats2half2_rn(v0, v1);
        outw[i] = *(uint32_t*)&h;
    }
    ((uint4*)(g_c + (size_t)warp * CAT + H4))[lane] = *(uint4*)outw;
}

// ---------------- readout normalize ----------------
__global__ void k_norm(float* __restrict__ out) {
    int b = blockIdx.x;
    int t = threadIdx.x;  // 128 threads
    float v = g_readout[b * OUTD + t];
    float ss = v * v;
#pragma unroll
    for (int o = 16; o > 0; o >>= 1) ss += __shfl_xor_sync(0xffffffffu, ss, o);
    __shared__ float sw[4];
    if ((t & 31) == 0) sw[t >> 5] = ss;
    __syncthreads();
    float tot = sw[0] + sw[1] + sw[2] + sw[3];
    float norm = fmaxf(sqrtf(tot), 1e-12f);
    out[b * OUTD + t] = v / norm;
}

// ---------------- launch ----------------
extern "C" void kernel_launch(void* const* d_in, const int* in_sizes, int n_in,
                              void* d_out, int out_size) {
    const float* x    = (const float*)d_in[0];
    const float* w    = (const float*)d_in[1];
    const float* W1   = (const float*)d_in[2];
    const float* fc1W = (const float*)d_in[3];
    const float* gam  = (const float*)d_in[4];
    const float* bet  = (const float*)d_in[5];
    const float* W2   = (const float*)d_in[6];
    const float* W3   = (const float*)d_in[7];
    const int*   src  = (const int*)d_in[8];
    const int*   dst  = (const int*)d_in[9];
    const int*   gid  = (const int*)d_in[10];
    float* out = (float*)d_out;

    __half *p_bh, *p_xh, *p_a1, *p_c, *p_f1h, *p_y2, *p_x2, *p_y3;
    cudaGetSymbolAddress((void**)&p_bh, g_bh);
    cudaGetSymbolAddress((void**)&p_xh, g_xh);
    cudaGetSymbolAddress((void**)&p_a1, g_a1);
    cudaGetSymbolAddress((void**)&p_c, g_c);
    cudaGetSymbolAddress((void**)&p_f1h, g_f1h);
    cudaGetSymbolAddress((void**)&p_y2, g_y2);
    cudaGetSymbolAddress((void**)&p_x2, g_x2);
    cudaGetSymbolAddress((void**)&p_y3, g_y3);

    const int SMEM = 61440;
    cudaFuncSetAttribute(k_mma<128, 1>, cudaFuncAttributeMaxDynamicSharedMemorySize, SMEM);
    cudaFuncSetAttribute(k_mma<128, 2>, cudaFuncAttributeMaxDynamicSharedMemorySize, SMEM);
    cudaFuncSetAttribute(k_mma<512, 2>, cudaFuncAttributeMaxDynamicSharedMemorySize, SMEM);
    cudaFuncSetAttribute(k_mma<256, 2>, cudaFuncAttributeMaxDynamicSharedMemorySize, SMEM);

    const int TB = 256;
    // preprocessing (5 launches; launch #6 is the first heavy agg -> ncu profiles it)
    k_zero_conv<<<(WTOT + NP * IND + TB - 1) / TB, TB>>>(W1, fc1W, W2, W3, x);
    k_deg<<<(NE + TB - 1) / TB, TB>>>(src, dst);
    k_scan_a<<<40, 1024>>>();
    k_scan_c<<<40, 1024>>>();
    k_place<<<(NE + TB - 1) / TB, TB>>>(src, dst, w);

    const int AGG_BLK = (NP * 32 + TB - 1) / TB;
    const int GX = NP / 128;  // 313

    // layer 1: agg(x_fp16) -> fp16 plane, GEMM 128->256 relu+fp16 into cat[:,0:256)
    k_agg<IND, 0><<<AGG_BLK, TB>>>(p_xh, p_a1, nullptr);
    k_mma<128, 1><<<dim3(GX, 2), TB, SMEM>>>(p_a1, p_bh + 0, p_c, CAT, 0);
    // fc1: GEMM raw fp16 -> f1h, then LN+relu+fp16 into cat[:,256:512)
    k_mma<128, 2><<<dim3(GX, 2), TB, SMEM>>>(p_xh, p_bh + 32768, p_f1h, H4, 0);
    k_ln<<<AGG_BLK, TB>>>(gam, bet);
    // layer 2: GEMM 512->256 raw fp16, agg(fp16) + relu -> fp16 plane
    k_mma<512, 2><<<dim3(GX, 2), TB, SMEM>>>(p_c, p_bh + 65536, p_y2, H4, 0);
    k_agg<H4, 1><<<AGG_BLK, TB>>>(p_y2, p_x2, nullptr);
    // layer 3: GEMM 256->128 raw fp16, agg(fp16) + relu + readout
    k_mma<256, 2><<<dim3(GX, 1), TB, SMEM>>>(p_x2, p_bh + 196608, p_y3, OUTD, 0);
    k_agg<OUTD, 2><<<AGG_BLK, TB>>>(p_y3, nullptr, gid);
    // final L2 normalize
    k_norm<<<NG, OUTD>>>(out);
}

// round 10
// speedup vs baseline: 1.1628x; 1.0063x over previous
#include <cuda_runtime.h>
#include <cuda_fp16.h>
#include <cstdint>

#define NN 40000
#define NP 40064   // 313 * 128, padded row count
#define NE 320000
#define NG 64
#define IND 128
#define H4 256
#define OUTD 128
#define CAT 512

// ---------------- scratch (device globals; no allocation allowed) ----------------
__device__ int   g_outcnt[NN];
__device__ int   g_incnt[NN];
__device__ int   g_cursor[NN];
__device__ int   g_rowptr[NN + 1];
__device__ int   g_bsum[64];
__device__ float g_outinv[NN];
__device__ float g_ininv[NN];
__device__ int2  g_ep[NE];           // packed {src, coef_bits}, CSR-ordered by dst
__device__ float g_readout[NG * OUTD];
// fp16 activations (padded to NP rows)
__device__ __half g_xh[NP * IND];    // x as fp16
__device__ __half g_a1[NP * IND];    // agg1
__device__ __half g_c[NP * CAT];     // concat [x1 | f1]
__device__ __half g_y2[NP * H4];     // layer2 GEMM out (pre-agg)
__device__ __half g_x2[NP * H4];     // x2
__device__ __half g_y3[NP * OUTD];   // layer3 GEMM out (pre-agg)
// weights fp16, transposed to [N][K]
// layout: W1 @0 (32768), fc1 @32768 (32768), W2 @65536 (131072), W3 @196608 (32768)
__device__ __half g_bh[229376];

// ---------------- helpers ----------------
__device__ __forceinline__ uint32_t smem_u32(const void* p) {
    uint32_t a;
    asm("{ .reg .u64 t; cvta.to.shared.u64 t, %1; cvt.u32.u64 %0, t; }" : "=r"(a) : "l"(p));
    return a;
}
__device__ __forceinline__ void cpa16(uint32_t dst, const void* src) {
    asm volatile("cp.async.cg.shared.global [%0], [%1], 16;" :: "r"(dst), "l"(src) : "memory");
}
__device__ __forceinline__ void cpa_commit() {
    asm volatile("cp.async.commit_group;" ::: "memory");
}
#define MMA16816(d, a, b)                                                     \
    asm volatile(                                                             \
        "mma.sync.aligned.m16n8k16.row.col.f32.f16.f16.f32 "                  \
        "{%0,%1,%2,%3}, {%4,%5,%6,%7}, {%8,%9}, {%0,%1,%2,%3};"               \
        : "+f"((d)[0]), "+f"((d)[1]), "+f"((d)[2]), "+f"((d)[3])              \
        : "r"((a)[0]), "r"((a)[1]), "r"((a)[2]), "r"((a)[3]),                 \
          "r"((b)[0]), "r"((b)[1]))
#define LDSM4(R, addr)                                                        \
    asm volatile("ldmatrix.sync.aligned.m8n8.x4.shared.b16 {%0,%1,%2,%3}, [%4];" \
        : "=r"((R)[0]), "=r"((R)[1]), "=r"((R)[2]), "=r"((R)[3]) : "r"(addr))

// ---------------- setup kernels ----------------
#define WTOT 229376
__global__ void k_zero_conv(const float* __restrict__ W1, const float* __restrict__ F1,
                            const float* __restrict__ W2, const float* __restrict__ W3,
                            const float* __restrict__ x) {
    int idx = blockIdx.x * blockDim.x + threadIdx.x;
    if (idx < NN) { g_outcnt[idx] = 0; g_incnt[idx] = 0; g_cursor[idx] = 0; }
    if (idx < NG * OUTD) g_readout[idx] = 0.f;
    if (idx < WTOT) {
        const float* W; int K, N, base;
        if (idx < 32768)       { W = W1; K = 128; N = 256; base = 0; }
        else if (idx < 65536)  { W = F1; K = 128; N = 256; base = 32768; }
        else if (idx < 196608) { W = W2; K = 512; N = 256; base = 65536; }
        else                   { W = W3; K = 256; N = 128; base = 196608; }
        int li = idx - base;
        int k = li % K, n = li / K;
        g_bh[idx] = __float2half_rn(W[k * N + n]);
    } else {
        int j = idx - WTOT;
        if (j < NP * IND) {
            float v = (j < NN * IND) ? x[j] : 0.f;
            g_xh[j] = __float2half_rn(v);
        }
    }
}

__global__ void k_deg(const int* __restrict__ src, const int* __restrict__ dst) {
    int e = blockIdx.x * blockDim.x + threadIdx.x;
    if (e < NE) {
        atomicAdd(&g_outcnt[src[e]], 1);
        atomicAdd(&g_incnt[dst[e]], 1);
    }
}

__global__ void k_scan_a() {
    __shared__ int sh[1024];
    int b = blockIdx.x, t = threadIdx.x;
    int idx = b * 1024 + t;
    int v = (idx < NN) ? g_incnt[idx] : 0;
    if (idx < NN) {
        g_ininv[idx]  = rsqrtf((float)max(v, 1));
        g_outinv[idx] = rsqrtf((float)max(g_outcnt[idx], 1));
    }
    sh[t] = v;
    __syncthreads();
#pragma unroll
    for (int off = 1; off < 1024; off <<= 1) {
        int u = (t >= off) ? sh[t - off] : 0;
        __syncthreads();
        sh[t] += u;
        __syncthreads();
    }
    int incl = sh[t];
    if (idx <= NN) g_rowptr[idx] = incl - v;
    if (t == 1023) g_bsum[b] = incl;
}
__global__ void k_scan_c() {
    __shared__ int sbs[40];
    __shared__ int pre;
    int b = blockIdx.x, t = threadIdx.x;
    if (t < 40) sbs[t] = g_bsum[t];
    __syncthreads();
    if (t == 0) {
        int s = 0;
        for (int i = 0; i < b; i++) s += sbs[i];
        pre = s;
    }
    __syncthreads();
    int idx = b * 1024 + t;
    if (idx <= NN) g_rowptr[idx] += pre;
}

__global__ void k_place(const int* __restrict__ src, const int* __restrict__ dst,
                        const float* __restrict__ w) {
    int e = blockIdx.x * blockDim.x + threadIdx.x;
    if (e >= NE) return;
    float4 ww = *(const float4*)(w + 4 * e);
    float m = fmaxf(fmaxf(ww.x, ww.y), fmaxf(ww.z, ww.w));
    int d = dst[e];
    int s = src[e];
    int pos = g_rowptr[d] + atomicAdd(&g_cursor[d], 1);
    g_ep[pos] = make_int2(s, __float_as_int(m * g_outinv[s]));
}

// ---------------- aggregation: one warp per dst node, fp16 gather, packed edges ----------------
// MODE 0: fp16 out (no relu); MODE 1: relu + fp16 out; MODE 2: relu + readout atomics
template <int D, int MODE>
__global__ void k_agg(const __half* __restrict__ in, __half* __restrict__ oh,
                      const int* __restrict__ gid) {
    int warp = (blockIdx.x * blockDim.x + threadIdx.x) >> 5;
    int lane = threadIdx.x & 31;
    if (warp >= NP) return;
    constexpr int V = D / 64;  // half2 units per lane
    if (warp >= NN) {
        if (MODE != 2) {
            uint32_t* ph = (uint32_t*)(oh + (size_t)warp * D);
#pragma unroll
            for (int v = 0; v < V; v++) ph[lane * V + v] = 0;
        }
        return;
    }
    int beg = g_rowptr[warp];
    int end = g_rowptr[warp + 1];
    float2 acc[V];
#pragma unroll
    for (int v = 0; v < V; v++) acc[v] = make_float2(0.f, 0.f);
    int e = beg;
    for (; e + 3 < end; e += 4) {  // 4-way unroll for MLP
        int2 p0 = g_ep[e], p1 = g_ep[e + 1], p2 = g_ep[e + 2], p3 = g_ep[e + 3];
        const uint32_t* q0 = (const uint32_t*)(in + (size_t)p0.x * D) + lane * V;
        const uint32_t* q1 = (const uint32_t*)(in + (size_t)p1.x * D) + lane * V;
        const uint32_t* q2 = (const uint32_t*)(in + (size_t)p2.x * D) + lane * V;
        const uint32_t* q3 = (const uint32_t*)(in + (size_t)p3.x * D) + lane * V;
        float c0 = __int_as_float(p0.y), c1 = __int_as_float(p1.y);
        float c2 = __int_as_float(p2.y), c3 = __int_as_float(p3.y);
        uint32_t t0[V], t1[V], t2[V], t3[V];
#pragma unroll
        for (int v = 0; v < V; v++) { t0[v] = q0[v]; t1[v] = q1[v]; t2[v] = q2[v]; t3[v] = q3[v]; }
#pragma unroll
        for (int v = 0; v < V; v++) {
            float2 f0 = __half22float2(*(const __half2*)&t0[v]);
            float2 f1 = __half22float2(*(const __half2*)&t1[v]);
            float2 f2 = __half22float2(*(const __half2*)&t2[v]);
            float2 f3 = __half22float2(*(const __half2*)&t3[v]);
            acc[v].x = fmaf(c0, f0.x, fmaf(c1, f1.x, fmaf(c2, f2.x, fmaf(c3, f3.x, acc[v].x))));
            acc[v].y = fmaf(c0, f0.y, fmaf(c1, f1.y, fmaf(c2, f2.y, fmaf(c3, f3.y, acc[v].y))));
        }
    }
    for (; e < end; e++) {
        int2 p = g_ep[e];
        float c = __int_as_float(p.y);
        const uint32_t* q = (const uint32_t*)(in + (size_t)p.x * D) + lane * V;
#pragma unroll
        for (int v = 0; v < V; v++) {
            uint32_t t = q[v];
            float2 f = __half22float2(*(const __half2*)&t);
            acc[v].x = fmaf(c, f.x, acc[v].x);
            acc[v].y = fmaf(c, f.y, acc[v].y);
        }
    }
    float inv = g_ininv[warp];
#pragma unroll
    for (int v = 0; v < V; v++) {
        acc[v].x *= inv; acc[v].y *= inv;
        if (MODE >= 1) {
            acc[v].x = fmaxf(acc[v].x, 0.f);
            acc[v].y = fmaxf(acc[v].y, 0.f);
        }
    }
    if (MODE == 2) {
        int g = gid[warp];
        float* r = g_readout + g * OUTD + lane * 4;
        atomicAdd(r + 0, acc[0].x);
        atomicAdd(r + 1, acc[0].y);
        atomicAdd(r + 2, acc[1].x);
        atomicAdd(r + 3, acc[1].y);
    } else {
        uint32_t* ph = (uint32_t*)(oh + (size_t)warp * D);
#pragma unroll
        for (int v = 0; v < V; v++) {
            __half2 a = __floats2half2_rn(acc[v].x, acc[v].y);
            ph[lane * V + v] = *(uint32_t*)&a;
        }
    }
}

// ---------------- fp16 single-pass mma.sync GEMM, 3-stage pipeline ----------------
// Block tile 128x128, BK=32/stage, 3 stages, one sync per chunk. 80B-padded smem rows.
// EPI: 1 = relu + fp16 out, 2 = raw fp16 out
template <int K, int EPI>
__global__ __launch_bounds__(256, 2) void k_mma(
    const __half* __restrict__ Ah, const __half* __restrict__ Bh,
    __half* __restrict__ Ch, int ldC, int colOff) {
    extern __shared__ __align__(16) uint8_t smem[];
    constexpr int NC = K / 32;
    constexpr uint32_t AH_ = 0, BH_ = 10240, STG = 20480;
    const int tid = threadIdx.x;
    const int wid = tid >> 5, lane = tid & 31;
    const int wm = wid & 3, wn = wid >> 2;
    const int m0 = blockIdx.x * 128;
    const int nblk = blockIdx.y * 128;
    const uint32_t sb = smem_u32(smem);

    float acc[2][8][4];
#pragma unroll
    for (int mi = 0; mi < 2; mi++)
#pragma unroll
        for (int ni = 0; ni < 8; ni++)
#pragma unroll
            for (int r = 0; r < 4; r++) acc[mi][ni][r] = 0.f;

    const int lrow = tid & 127;
    const bool isB = tid >= 128;
    const __half* gS = isB ? (Bh + (size_t)(nblk + lrow) * K)
                           : (Ah + (size_t)(m0 + lrow) * K);
    const uint32_t gD = (isB ? BH_ : AH_) + (uint32_t)lrow * 80;

    const uint32_t aoff = AH_ + (uint32_t)(wm * 32 + (lane & 7) + ((lane >> 3) & 1) * 8) * 80 +
                          (lane >> 4) * 16;
    const uint32_t boff = BH_ + (uint32_t)(wn * 64 + ((lane >> 4) & 1) * 8 + (lane & 7)) * 80 +
                          ((lane >> 3) & 1) * 16;

    {
        uint32_t st = sb;
        const __half* gp = gS;
#pragma unroll
        for (int j = 0; j < 4; j++) cpa16(st + gD + j * 16, gp + j * 8);
        cpa_commit();
        st = sb + STG;
        gp = gS + 32;
#pragma unroll
        for (int j = 0; j < 4; j++) cpa16(st + gD + j * 16, gp + j * 8);
        cpa_commit();
    }

    for (int c = 0; c < NC; c++) {
        if (c + 1 < NC)
            asm volatile("cp.async.wait_group 1;" ::: "memory");
        else
            asm volatile("cp.async.wait_group 0;" ::: "memory");
        __syncthreads();
        if (c + 2 < NC) {
            uint32_t st = sb + ((c + 2) % 3) * STG;
            const __half* gp = gS + (c + 2) * 32;
#pragma unroll
            for (int j = 0; j < 4; j++) cpa16(st + gD + j * 16, gp + j * 8);
            cpa_commit();
        }
        uint32_t st = sb + (c % 3) * STG;
#pragma unroll
        for (int kk = 0; kk < 2; kk++) {
            const uint32_t ko = kk * 32;
            uint32_t af[2][4], bf[8][2];
#pragma unroll
            for (int mi = 0; mi < 2; mi++) LDSM4(af[mi], st + aoff + mi * 1280 + ko);
#pragma unroll
            for (int p = 0; p < 4; p++) {
                uint32_t r4[4];
                LDSM4(r4, st + boff + p * 1280 + ko);
                bf[2 * p][0] = r4[0]; bf[2 * p][1] = r4[1];
                bf[2 * p + 1][0] = r4[2]; bf[2 * p + 1][1] = r4[3];
            }
#pragma unroll
            for (int mi = 0; mi < 2; mi++)
#pragma unroll
                for (int ni = 0; ni < 8; ni++) MMA16816(acc[mi][ni], af[mi], bf[ni]);
        }
    }

    const int g = lane >> 2, q = lane & 3;
#pragma unroll
    for (int mi = 0; mi < 2; mi++)
#pragma unroll
        for (int ni = 0; ni < 8; ni++) {
            int r0 = m0 + wm * 32 + mi * 16 + g;
            int cc = colOff + nblk + wn * 64 + ni * 8 + 2 * q;
            float v0 = acc[mi][ni][0], v1 = acc[mi][ni][1];
            float v2 = acc[mi][ni][2], v3 = acc[mi][ni][3];
            if (EPI == 1) {
                v0 = fmaxf(v0, 0.f); v1 = fmaxf(v1, 0.f);
                v2 = fmaxf(v2, 0.f); v3 = fmaxf(v3, 0.f);
            }
            __half2 a = __floats2half2_rn(v0, v1);
            __half2 b = __floats2half2_rn(v2, v3);
            *(__half2*)(Ch + (size_t)r0 * ldC + cc) = a;
            *(__half2*)(Ch + (size_t)(r0 + 8) * ldC + cc) = b;
        }
}

// ---------------- fc1 GEMM (K=128, full N=256 per CTA) + fused LayerNorm + ReLU ----------------
// Block tile 64x256, 8 warps in 2x4, warp tile 32x64. Writes fp16 into c cols [256,512).
__global__ __launch_bounds__(256, 2) void k_mma_fc1(
    const __half* __restrict__ Ah, const __half* __restrict__ Bh,
    __half* __restrict__ Ch,
    const float* __restrict__ gamma, const float* __restrict__ beta) {
    extern __shared__ __align__(16) uint8_t smem[];
    constexpr int NC = 4;  // K=128 / 32
    constexpr uint32_t AH_ = 0, BH_ = 5120, STG = 25600;
    const int tid = threadIdx.x;
    const int wid = tid >> 5, lane = tid & 31;
    const int wm = wid & 1, wn = wid >> 1;  // 2 x 4
    const int m0 = blockIdx.x * 64;
    const uint32_t sb = smem_u32(smem);

    float acc[2][8][4];
#pragma unroll
    for (int mi = 0; mi < 2; mi++)
#pragma unroll
        for (int ni = 0; ni < 8; ni++)
#pragma unroll
            for (int r = 0; r < 4; r++) acc[mi][ni][r] = 0.f;

    // loaders: every thread loads B row tid; threads <64 also load A row tid
    const __half* bSrc = Bh + (size_t)tid * 128;
    const uint32_t bDst = BH_ + (uint32_t)tid * 80;
    const __half* aSrc = Ah + (size_t)(m0 + tid) * 128;  // valid only tid<64
    const uint32_t aDst = AH_ + (uint32_t)tid * 80;
    const bool isA = tid < 64;

    const uint32_t aoff = AH_ + (uint32_t)(wm * 32 + (lane & 7) + ((lane >> 3) & 1) * 8) * 80 +
                          (lane >> 4) * 16;
    const uint32_t boff = BH_ + (uint32_t)(wn * 64 + ((lane >> 4) & 1) * 8 + (lane & 7)) * 80 +
                          ((lane >> 3) & 1) * 16;

#pragma unroll
    for (int s = 0; s < 2; s++) {
        uint32_t st = sb + s * STG;
#pragma unroll
        for (int j = 0; j < 4; j++) cpa16(st + bDst + j * 16, bSrc + s * 32 + j * 8);
        if (isA)
#pragma unroll
            for (int j = 0; j < 4; j++) cpa16(st + aDst + j * 16, aSrc + s * 32 + j * 8);
        cpa_commit();
    }

    for (int c = 0; c < NC; c++) {
        if (c + 1 < NC)
            asm volatile("cp.async.wait_group 1;" ::: "memory");
        else
            asm volatile("cp.async.wait_group 0;" ::: "memory");
        __syncthreads();
        if (c + 2 < NC) {
            uint32_t st = sb + ((c + 2) % 3) * STG;
#pragma unroll
            for (int j = 0; j < 4; j++) cpa16(st + bDst + j * 16, bSrc + (c + 2) * 32 + j * 8);
            if (isA)
#pragma unroll
                for (int j = 0; j < 4; j++) cpa16(st + aDst + j * 16, aSrc + (c + 2) * 32 + j * 8);
            cpa_commit();
        }
        uint32_t st = sb + (c % 3) * STG;
#pragma unroll
        for (int kk = 0; kk < 2; kk++) {
            const uint32_t ko = kk * 32;
            uint32_t af[2][4], bf[8][2];
#pragma unroll
            for (int mi = 0; mi < 2; mi++) LDSM4(af[mi], st + aoff + mi * 1280 + ko);
#pragma unroll
            for (int p = 0; p < 4; p++) {
                uint32_t r4[4];
                LDSM4(r4, st + boff + p * 1280 + ko);
                bf[2 * p][0] = r4[0]; bf[2 * p][1] = r4[1];
                bf[2 * p + 1][0] = r4[2]; bf[2 * p + 1][1] = r4[3];
            }
#pragma unroll
            for (int mi = 0; mi < 2; mi++)
#pragma unroll
                for (int ni = 0; ni < 8; ni++) MMA16816(acc[mi][ni], af[mi], bf[ni]);
        }
    }

    // ---- fused LayerNorm over 256 cols ----
    __syncthreads();  // all warps done reading smem stages
    float2* part = (float2*)smem;  // [64 rows][4 wn]
    const int g = lane >> 2, q = lane & 3;
    // per-thread partial sums over its 16 values per row (8 ni x 2 cols)
#pragma unroll
    for (int mi = 0; mi < 2; mi++) {
        float s0 = 0.f, ss0 = 0.f, s8 = 0.f, ss8 = 0.f;
#pragma unroll
        for (int ni = 0; ni < 8; ni++) {
            float v0 = acc[mi][ni][0], v1 = acc[mi][ni][1];
            float v2 = acc[mi][ni][2], v3 = acc[mi][ni][3];
            s0 += v0 + v1; ss0 += v0 * v0 + v1 * v1;
            s8 += v2 + v3; ss8 += v2 * v2 + v3 * v3;
        }
        // reduce across q (4 lanes)
#pragma unroll
        for (int o = 1; o < 4; o <<= 1) {
            s0 += __shfl_xor_sync(0xffffffffu, s0, o);
            ss0 += __shfl_xor_sync(0xffffffffu, ss0, o);
            s8 += __shfl_xor_sync(0xffffffffu, s8, o);
            ss8 += __shfl_xor_sync(0xffffffffu, ss8, o);
        }
        if (q == 0) {
            int lr = wm * 32 + mi * 16 + g;
            part[lr * 4 + wn] = make_float2(s0, ss0);
            part[(lr + 8) * 4 + wn] = make_float2(s8, ss8);
        }
    }
    __syncthreads();
#pragma unroll
    for (int mi = 0; mi < 2; mi++) {
        int lr = wm * 32 + mi * 16 + g;
        float2 a0 = part[lr * 4 + 0], a1 = part[lr * 4 + 1];
        float2 a2 = part[lr * 4 + 2], a3 = part[lr * 4 + 3];
        float s = a0.x + a1.x + a2.x + a3.x;
        float ss = a0.y + a1.y + a2.y + a3.y;
        float mean0 = s * (1.f / 256.f);
        float rstd0 = rsqrtf(ss * (1.f / 256.f) - mean0 * mean0 + 1e-5f);
        a0 = part[(lr + 8) * 4 + 0]; a1 = part[(lr + 8) * 4 + 1];
        a2 = part[(lr + 8) * 4 + 2]; a3 = part[(lr + 8) * 4 + 3];
        s = a0.x + a1.x + a2.x + a3.x;
        ss = a0.y + a1.y + a2.y + a3.y;
        float mean8 = s * (1.f / 256.f);
        float rstd8 = rsqrtf(ss * (1.f / 256.f) - mean8 * mean8 + 1e-5f);
        int r0 = m0 + lr;
#pragma unroll
        for (int ni = 0; ni < 8; ni++) {
            int col = wn * 64 + ni * 8 + 2 * q;
            float2 gg = *(const float2*)(gamma + col);
            float2 bb = *(const float2*)(beta + col);
            float v0 = fmaxf((acc[mi][ni][0] - mean0) * rstd0 * gg.x + bb.x, 0.f);
            float v1 = fmaxf((acc[mi][ni][1] - mean0) * rstd0 * gg.y + bb.y, 0.f);
            float v2 = fmaxf((acc[mi][ni][2] - mean8) * rstd8 * gg.x + bb.x, 0.f);
            float v3 = fmaxf((acc[mi][ni][3] - mean8) * rstd8 * gg.y + bb.y, 0.f);
            __half2 h0 = __floats2half2_rn(v0, v1);
            __half2 h1 = __floats2half2_rn(v2, v3);
            *(__half2*)(Ch + (size_t)r0 * CAT + H4 + col) = h0;
            *(__half2*)(Ch + (size_t)(r0 + 8) * CAT + H4 + col) = h1;
        }
    }
}

// ---------------- readout normalize ----------------
__global__ void k_norm(float* __restrict__ out) {
    int b = blockIdx.x;
    int t = threadIdx.x;  // 128 threads
    float v = g_readout[b * OUTD + t];
    float ss = v * v;
#pragma unroll
    for (int o = 16; o > 0; o >>= 1) ss += __shfl_xor_sync(0xffffffffu, ss, o);
    __shared__ float sw[4];
    if ((t & 31) == 0) sw[t >> 5] = ss;
    __syncthreads();
    float tot = sw[0] + sw[1] + sw[2] + sw[3];
    float norm = fmaxf(sqrtf(tot), 1e-12f);
    out[b * OUTD + t] = v / norm;
}

// ---------------- launch ----------------
extern "C" void kernel_launch(void* const* d_in, const int* in_sizes, int n_in,
                              void* d_out, int out_size) {
    const float* x    = (const float*)d_in[0];
    const float* w    = (const float*)d_in[1];
    const float* W1   = (const float*)d_in[2];
    const float* fc1W = (const float*)d_in[3];
    const float* gam  = (const float*)d_in[4];
    const float* bet  = (const float*)d_in[5];
    const float* W2   = (const float*)d_in[6];
    const float* W3   = (const float*)d_in[7];
    const int*   src  = (const int*)d_in[8];
    const int*   dst  = (const int*)d_in[9];
    const int*   gid  = (const int*)d_in[10];
    float* out = (float*)d_out;

    __half *p_bh, *p_xh, *p_a1, *p_c, *p_y2, *p_x2, *p_y3;
    cudaGetSymbolAddress((void**)&p_bh, g_bh);
    cudaGetSymbolAddress((void**)&p_xh, g_xh);
    cudaGetSymbolAddress((void**)&p_a1, g_a1);
    cudaGetSymbolAddress((void**)&p_c, g_c);
    cudaGetSymbolAddress((void**)&p_y2, g_y2);
    cudaGetSymbolAddress((void**)&p_x2, g_x2);
    cudaGetSymbolAddress((void**)&p_y3, g_y3);

    const int SMEM = 61440;
    const int SMEM_FC1 = 76800;
    cudaFuncSetAttribute(k_mma<128, 1>, cudaFuncAttributeMaxDynamicSharedMemorySize, SMEM);
    cudaFuncSetAttribute(k_mma<512, 2>, cudaFuncAttributeMaxDynamicSharedMemorySize, SMEM);
    cudaFuncSetAttribute(k_mma<256, 2>, cudaFuncAttributeMaxDynamicSharedMemorySize, SMEM);
    cudaFuncSetAttribute(k_mma_fc1, cudaFuncAttributeMaxDynamicSharedMemorySize, SMEM_FC1);

    const int TB = 256;
    // preprocessing
    k_zero_conv<<<(WTOT + NP * IND + TB - 1) / TB, TB>>>(W1, fc1W, W2, W3, x);
    k_deg<<<(NE + TB - 1) / TB, TB>>>(src, dst);
    k_scan_a<<<40, 1024>>>();
    k_scan_c<<<40, 1024>>>();
    k_place<<<(NE + TB - 1) / TB, TB>>>(src, dst, w);

    const int AGG_BLK = (NP * 32 + TB - 1) / TB;
    const int GX = NP / 128;   // 313
    const int GX64 = NP / 64;  // 626

    // layer 1: agg(x_fp16) -> fp16 plane, GEMM 128->256 relu+fp16 into cat[:,0:256)
    k_agg<IND, 0><<<AGG_BLK, TB>>>(p_xh, p_a1, nullptr);
    k_mma<128, 1><<<dim3(GX, 2), TB, SMEM>>>(p_a1, p_bh + 0, p_c, CAT, 0);
    // fc1: GEMM + fused LN + relu, fp16 into cat[:,256:512)
    k_mma_fc1<<<GX64, TB, SMEM_FC1>>>(p_xh, p_bh + 32768, p_c, gam, bet);
    // layer 2: GEMM 512->256 raw fp16, agg(fp16) + relu -> fp16 plane
    k_mma<512, 2><<<dim3(GX, 2), TB, SMEM>>>(p_c, p_bh + 65536, p_y2, H4, 0);
    k_agg<H4, 1><<<AGG_BLK, TB>>>(p_y2, p_x2, nullptr);
    // layer 3: GEMM 256->128 raw fp16, agg(fp16) + relu + readout
    k_mma<256, 2><<<dim3(GX, 1), TB, SMEM>>>(p_x2, p_bh + 196608, p_y3, OUTD, 0);
    k_agg<OUTD, 2><<<AGG_BLK, TB>>>(p_y3, nullptr, gid);
    // final L2 normalize
    k_norm<<<NG, OUTD>>>(out);
}

// round 11
// speedup vs baseline: 1.2580x; 1.0818x over previous
#include <cuda_runtime.h>
#include <cuda_fp16.h>
#include <cstdint>

#define NN 40000
#define NP 40064   // 313 * 128, padded row count
#define NE 320000
#define NG 64
#define IND 128
#define H4 256
#define OUTD 128
#define CAT 512

// ---------------- scratch (device globals; no allocation allowed) ----------------
__device__ int   g_outcnt[NN];
__device__ int   g_incnt[NN];
__device__ int   g_cursor[NN];
__device__ int   g_rowptr[NN + 1];
__device__ int   g_bsum[64];
__device__ float g_outinv[NN];
__device__ float g_ininv[NN];
__device__ int2  g_ep[NE];           // packed {src, coef_bits}, CSR-ordered by dst
__device__ float g_readout[NG * OUTD];
// fp16 activations (padded to NP rows)
__device__ __half g_xh[NP * IND];    // x as fp16
__device__ __half g_a1[NP * IND];    // agg1
__device__ __half g_c[NP * CAT];     // concat [x1 | f1]
__device__ __half g_y2[NP * H4];     // layer2 GEMM out (pre-agg)
__device__ __half g_x2[NP * H4];     // x2
__device__ __half g_y3[NP * OUTD];   // layer3 GEMM out (pre-agg)
// weights fp16, transposed to [N][K]
// layout: W1 @0 (32768), fc1 @32768 (32768), W2 @65536 (131072), W3 @196608 (32768)
__device__ __half g_bh[229376];

// ---------------- helpers ----------------
template <int V> struct VecSel;
template <> struct VecSel<2> { using T = uint2; };
template <> struct VecSel<4> { using T = uint4; };

__device__ __forceinline__ uint32_t smem_u32(const void* p) {
    uint32_t a;
    asm("{ .reg .u64 t; cvta.to.shared.u64 t, %1; cvt.u32.u64 %0, t; }" : "=r"(a) : "l"(p));
    return a;
}
__device__ __forceinline__ void cpa16(uint32_t dst, const void* src) {
    asm volatile("cp.async.cg.shared.global [%0], [%1], 16;" :: "r"(dst), "l"(src) : "memory");
}
__device__ __forceinline__ void cpa_commit() {
    asm volatile("cp.async.commit_group;" ::: "memory");
}
#define MMA16816(d, a, b)                                                     \
    asm volatile(                                                             \
        "mma.sync.aligned.m16n8k16.row.col.f32.f16.f16.f32 "                  \
        "{%0,%1,%2,%3}, {%4,%5,%6,%7}, {%8,%9}, {%0,%1,%2,%3};"               \
        : "+f"((d)[0]), "+f"((d)[1]), "+f"((d)[2]), "+f"((d)[3])              \
        : "r"((a)[0]), "r"((a)[1]), "r"((a)[2]), "r"((a)[3]),                 \
          "r"((b)[0]), "r"((b)[1]))
#define LDSM4(R, addr)                                                        \
    asm volatile("ldmatrix.sync.aligned.m8n8.x4.shared.b16 {%0,%1,%2,%3}, [%4];" \
        : "=r"((R)[0]), "=r"((R)[1]), "=r"((R)[2]), "=r"((R)[3]) : "r"(addr))

// ---------------- setup kernels ----------------
#define WTOT 229376
__global__ void k_zero_conv(const float* __restrict__ W1, const float* __restrict__ F1,
                            const float* __restrict__ W2, const float* __restrict__ W3,
                            const float* __restrict__ x) {
    int idx = blockIdx.x * blockDim.x + threadIdx.x;
    if (idx < NN) { g_outcnt[idx] = 0; g_incnt[idx] = 0; g_cursor[idx] = 0; }
    if (idx < NG * OUTD) g_readout[idx] = 0.f;
    if (idx < WTOT) {
        const float* W; int K, N, base;
        if (idx < 32768)       { W = W1; K = 128; N = 256; base = 0; }
        else if (idx < 65536)  { W = F1; K = 128; N = 256; base = 32768; }
        else if (idx < 196608) { W = W2; K = 512; N = 256; base = 65536; }
        else                   { W = W3; K = 256; N = 128; base = 196608; }
        int li = idx - base;
        int k = li % K, n = li / K;
        g_bh[idx] = __float2half_rn(W[k * N + n]);
    } else {
        int j = idx - WTOT;
        if (j < NP * IND) {
            float v = (j < NN * IND) ? x[j] : 0.f;
            g_xh[j] = __float2half_rn(v);
        }
    }
}

__global__ void k_deg(const int* __restrict__ src, const int* __restrict__ dst) {
    int e = blockIdx.x * blockDim.x + threadIdx.x;
    if (e < NE) {
        atomicAdd(&g_outcnt[src[e]], 1);
        atomicAdd(&g_incnt[dst[e]], 1);
    }
}

__global__ void k_scan_a() {
    __shared__ int sh[1024];
    int b = blockIdx.x, t = threadIdx.x;
    int idx = b * 1024 + t;
    int v = (idx < NN) ? g_incnt[idx] : 0;
    if (idx < NN) {
        g_ininv[idx]  = rsqrtf((float)max(v, 1));
        g_outinv[idx] = rsqrtf((float)max(g_outcnt[idx], 1));
    }
    sh[t] = v;
    __syncthreads();
#pragma unroll
    for (int off = 1; off < 1024; off <<= 1) {
        int u = (t >= off) ? sh[t - off] : 0;
        __syncthreads();
        sh[t] += u;
        __syncthreads();
    }
    int incl = sh[t];
    if (idx <= NN) g_rowptr[idx] = incl - v;
    if (t == 1023) g_bsum[b] = incl;
}
__global__ void k_scan_c() {
    __shared__ int sbs[40];
    __shared__ int pre;
    int b = blockIdx.x, t = threadIdx.x;
    if (t < 40) sbs[t] = g_bsum[t];
    __syncthreads();
    if (t == 0) {
        int s = 0;
        for (int i = 0; i < b; i++) s += sbs[i];
        pre = s;
    }
    __syncthreads();
    int idx = b * 1024 + t;
    if (idx <= NN) g_rowptr[idx] += pre;
}

__global__ void k_place(const int* __restrict__ src, const int* __restrict__ dst,
                        const float* __restrict__ w) {
    int e = blockIdx.x * blockDim.x + threadIdx.x;
    if (e >= NE) return;
    float4 ww = *(const float4*)(w + 4 * e);
    float m = fmaxf(fmaxf(ww.x, ww.y), fmaxf(ww.z, ww.w));
    int d = dst[e];
    int s = src[e];
    int pos = g_rowptr[d] + atomicAdd(&g_cursor[d], 1);
    g_ep[pos] = make_int2(s, __float_as_int(m * g_outinv[s]));
}

// ---------------- aggregation: one warp per dst node, vectorized fp16 gather ----------------
// MODE 0: fp16 out (no relu); MODE 1: relu + fp16 out; MODE 2: relu + readout atomics
template <int D, int MODE>
__global__ void k_agg(const __half* __restrict__ in, __half* __restrict__ oh,
                      const int* __restrict__ gid) {
    constexpr int V = D / 64;  // uint32 (half2) units per lane
    using VT = typename VecSel<V>::T;
    int warp = (blockIdx.x * blockDim.x + threadIdx.x) >> 5;
    int lane = threadIdx.x & 31;
    if (warp >= NP) return;
    if (warp >= NN) {
        if (MODE != 2) {
            VT z = {};
            ((VT*)(oh + (size_t)warp * D))[lane] = z;
        }
        return;
    }
    int beg = g_rowptr[warp];
    int end = g_rowptr[warp + 1];
    float2 acc[V];
#pragma unroll
    for (int v = 0; v < V; v++) acc[v] = make_float2(0.f, 0.f);
    int e = beg;
    for (; e + 3 < end; e += 4) {  // 4-way unroll for MLP
        int2 p0 = g_ep[e], p1 = g_ep[e + 1], p2 = g_ep[e + 2], p3 = g_ep[e + 3];
        VT t0 = ((const VT*)(in + (size_t)p0.x * D))[lane];
        VT t1 = ((const VT*)(in + (size_t)p1.x * D))[lane];
        VT t2 = ((const VT*)(in + (size_t)p2.x * D))[lane];
        VT t3 = ((const VT*)(in + (size_t)p3.x * D))[lane];
        float c0 = __int_as_float(p0.y), c1 = __int_as_float(p1.y);
        float c2 = __int_as_float(p2.y), c3 = __int_as_float(p3.y);
        const uint32_t* w0 = (const uint32_t*)&t0;
        const uint32_t* w1 = (const uint32_t*)&t1;
        const uint32_t* w2 = (const uint32_t*)&t2;
        const uint32_t* w3 = (const uint32_t*)&t3;
#pragma unroll
        for (int v = 0; v < V; v++) {
            float2 f0 = __half22float2(*(const __half2*)&w0[v]);
            float2 f1 = __half22float2(*(const __half2*)&w1[v]);
            float2 f2 = __half22float2(*(const __half2*)&w2[v]);
            float2 f3 = __half22float2(*(const __half2*)&w3[v]);
            acc[v].x = fmaf(c0, f0.x, fmaf(c1, f1.x, fmaf(c2, f2.x, fmaf(c3, f3.x, acc[v].x))));
            acc[v].y = fmaf(c0, f0.y, fmaf(c1, f1.y, fmaf(c2, f2.y, fmaf(c3, f3.y, acc[v].y))));
        }
    }
    for (; e < end; e++) {
        int2 p = g_ep[e];
        float c = __int_as_float(p.y);
        VT t = ((const VT*)(in + (size_t)p.x * D))[lane];
        const uint32_t* w = (const uint32_t*)&t;
#pragma unroll
        for (int v = 0; v < V; v++) {
            float2 f = __half22float2(*(const __half2*)&w[v]);
            acc[v].x = fmaf(c, f.x, acc[v].x);
            acc[v].y = fmaf(c, f.y, acc[v].y);
        }
    }
    float inv = g_ininv[warp];
#pragma unroll
    for (int v = 0; v < V; v++) {
        acc[v].x *= inv; acc[v].y *= inv;
        if (MODE >= 1) {
            acc[v].x = fmaxf(acc[v].x, 0.f);
            acc[v].y = fmaxf(acc[v].y, 0.f);
        }
    }
    if (MODE == 2) {
        int g = gid[warp];
        float* r = g_readout + g * OUTD + lane * 4;
        atomicAdd(r + 0, acc[0].x);
        atomicAdd(r + 1, acc[0].y);
        atomicAdd(r + 2, acc[1].x);
        atomicAdd(r + 3, acc[1].y);
    } else {
        VT ov;
        uint32_t* ow = (uint32_t*)&ov;
#pragma unroll
        for (int v = 0; v < V; v++) {
            __half2 a = __floats2half2_rn(acc[v].x, acc[v].y);
            ow[v] = *(uint32_t*)&a;
        }
        ((VT*)(oh + (size_t)warp * D))[lane] = ov;
    }
}

// ---------------- fp16 single-pass mma.sync GEMM, 3-stage pipeline ----------------
// Block tile 128x128, BK=32/stage, 3 stages, one sync per chunk. 80B-padded smem rows.
// EPI: 1 = relu + fp16 out, 2 = raw fp16 out
template <int K, int EPI>
__global__ __launch_bounds__(256, 2) void k_mma(
    const __half* __restrict__ Ah, const __half* __restrict__ Bh,
    __half* __restrict__ Ch, int ldC, int colOff) {
    extern __shared__ __align__(16) uint8_t smem[];
    constexpr int NC = K / 32;
    constexpr uint32_t AH_ = 0, BH_ = 10240, STG = 20480;
    const int tid = threadIdx.x;
    const int wid = tid >> 5, lane = tid & 31;
    const int wm = wid & 3, wn = wid >> 2;
    const int m0 = blockIdx.x * 128;
    const int nblk = blockIdx.y * 128;
    const uint32_t sb = smem_u32(smem);

    float acc[2][8][4];
#pragma unroll
    for (int mi = 0; mi < 2; mi++)
#pragma unroll
        for (int ni = 0; ni < 8; ni++)
#pragma unroll
            for (int r = 0; r < 4; r++) acc[mi][ni][r] = 0.f;

    const int lrow = tid & 127;
    const bool isB = tid >= 128;
    const __half* gS = isB ? (Bh + (size_t)(nblk + lrow) * K)
                           : (Ah + (size_t)(m0 + lrow) * K);
    const uint32_t gD = (isB ? BH_ : AH_) + (uint32_t)lrow * 80;

    const uint32_t aoff = AH_ + (uint32_t)(wm * 32 + (lane & 7) + ((lane >> 3) & 1) * 8) * 80 +
                          (lane >> 4) * 16;
    const uint32_t boff = BH_ + (uint32_t)(wn * 64 + ((lane >> 4) & 1) * 8 + (lane & 7)) * 80 +
                          ((lane >> 3) & 1) * 16;

    {
        uint32_t st = sb;
        const __half* gp = gS;
#pragma unroll
        for (int j = 0; j < 4; j++) cpa16(st + gD + j * 16, gp + j * 8);
        cpa_commit();
        st = sb + STG;
        gp = gS + 32;
#pragma unroll
        for (int j = 0; j < 4; j++) cpa16(st + gD + j * 16, gp + j * 8);
        cpa_commit();
    }

    for (int c = 0; c < NC; c++) {
        if (c + 1 < NC)
            asm volatile("cp.async.wait_group 1;" ::: "memory");
        else
            asm volatile("cp.async.wait_group 0;" ::: "memory");
        __syncthreads();
        if (c + 2 < NC) {
            uint32_t st = sb + ((c + 2) % 3) * STG;
            const __half* gp = gS + (c + 2) * 32;
#pragma unroll
            for (int j = 0; j < 4; j++) cpa16(st + gD + j * 16, gp + j * 8);
            cpa_commit();
        }
        uint32_t st = sb + (c % 3) * STG;
#pragma unroll
        for (int kk = 0; kk < 2; kk++) {
            const uint32_t ko = kk * 32;
            uint32_t af[2][4], bf[8][2];
#pragma unroll
            for (int mi = 0; mi < 2; mi++) LDSM4(af[mi], st + aoff + mi * 1280 + ko);
#pragma unroll
            for (int p = 0; p < 4; p++) {
                uint32_t r4[4];
                LDSM4(r4, st + boff + p * 1280 + ko);
                bf[2 * p][0] = r4[0]; bf[2 * p][1] = r4[1];
                bf[2 * p + 1][0] = r4[2]; bf[2 * p + 1][1] = r4[3];
            }
#pragma unroll
            for (int mi = 0; mi < 2; mi++)
#pragma unroll
                for (int ni = 0; ni < 8; ni++) MMA16816(acc[mi][ni], af[mi], bf[ni]);
        }
    }

    const int g = lane >> 2, q = lane & 3;
#pragma unroll
    for (int mi = 0; mi < 2; mi++)
#pragma unroll
        for (int ni = 0; ni < 8; ni++) {
            int r0 = m0 + wm * 32 + mi * 16 + g;
            int cc = colOff + nblk + wn * 64 + ni * 8 + 2 * q;
            float v0 = acc[mi][ni][0], v1 = acc[mi][ni][1];
            float v2 = acc[mi][ni][2], v3 = acc[mi][ni][3];
            if (EPI == 1) {
                v0 = fmaxf(v0, 0.f); v1 = fmaxf(v1, 0.f);
                v2 = fmaxf(v2, 0.f); v3 = fmaxf(v3, 0.f);
            }
            __half2 a = __floats2half2_rn(v0, v1);
            __half2 b = __floats2half2_rn(v2, v3);
            *(__half2*)(Ch + (size_t)r0 * ldC + cc) = a;
            *(__half2*)(Ch + (size_t)(r0 + 8) * ldC + cc) = b;
        }
}

// ---------------- fc1 GEMM (K=128, full N=256 per CTA) + fused LayerNorm + ReLU ----------------
// Block tile 64x256, 8 warps in 2x4, warp tile 32x64. Writes fp16 into c cols [256,512).
__global__ __launch_bounds__(256, 2) void k_mma_fc1(
    const __half* __restrict__ Ah, const __half* __restrict__ Bh,
    __half* __restrict__ Ch,
    const float* __restrict__ gamma, const float* __restrict__ beta) {
    extern __shared__ __align__(16) uint8_t smem[];
    constexpr int NC = 4;  // K=128 / 32
    constexpr uint32_t AH_ = 0, BH_ = 5120, STG = 25600;
    const int tid = threadIdx.x;
    const int wid = tid >> 5, lane = tid & 31;
    const int wm = wid & 1, wn = wid >> 1;  // 2 x 4
    const int m0 = blockIdx.x * 64;
    const uint32_t sb = smem_u32(smem);

    float acc[2][8][4];
#pragma unroll
    for (int mi = 0; mi < 2; mi++)
#pragma unroll
        for (int ni = 0; ni < 8; ni++)
#pragma unroll
            for (int r = 0; r < 4; r++) acc[mi][ni][r] = 0.f;

    const __half* bSrc = Bh + (size_t)tid * 128;
    const uint32_t bDst = BH_ + (uint32_t)tid * 80;
    const __half* aSrc = Ah + (size_t)(m0 + tid) * 128;  // valid only tid<64
    const uint32_t aDst = AH_ + (uint32_t)tid * 80;
    const bool isA = tid < 64;

    const uint32_t aoff = AH_ + (uint32_t)(wm * 32 + (lane & 7) + ((lane >> 3) & 1) * 8) * 80 +
                          (lane >> 4) * 16;
    const uint32_t boff = BH_ + (uint32_t)(wn * 64 + ((lane >> 4) & 1) * 8 + (lane & 7)) * 80 +
                          ((lane >> 3) & 1) * 16;

#pragma unroll
    for (int s = 0; s < 2; s++) {
        uint32_t st = sb + s * STG;
#pragma unroll
        for (int j = 0; j < 4; j++) cpa16(st + bDst + j * 16, bSrc + s * 32 + j * 8);
        if (isA)
#pragma unroll
            for (int j = 0; j < 4; j++) cpa16(st + aDst + j * 16, aSrc + s * 32 + j * 8);
        cpa_commit();
    }

    for (int c = 0; c < NC; c++) {
        if (c + 1 < NC)
            asm volatile("cp.async.wait_group 1;" ::: "memory");
        else
            asm volatile("cp.async.wait_group 0;" ::: "memory");
        __syncthreads();
        if (c + 2 < NC) {
            uint32_t st = sb + ((c + 2) % 3) * STG;
#pragma unroll
            for (int j = 0; j < 4; j++) cpa16(st + bDst + j * 16, bSrc + (c + 2) * 32 + j * 8);
            if (isA)
#pragma unroll
                for (int j = 0; j < 4; j++) cpa16(st + aDst + j * 16, aSrc + (c + 2) * 32 + j * 8);
            cpa_commit();
        }
        uint32_t st = sb + (c % 3) * STG;
#pragma unroll
        for (int kk = 0; kk < 2; kk++) {
            const uint32_t ko = kk * 32;
            uint32_t af[2][4], bf[8][2];
#pragma unroll
            for (int mi = 0; mi < 2; mi++) LDSM4(af[mi], st + aoff + mi * 1280 + ko);
#pragma unroll
            for (int p = 0; p < 4; p++) {
                uint32_t r4[4];
                LDSM4(r4, st + boff + p * 1280 + ko);
                bf[2 * p][0] = r4[0]; bf[2 * p][1] = r4[1];
                bf[2 * p + 1][0] = r4[2]; bf[2 * p + 1][1] = r4[3];
            }
#pragma unroll
            for (int mi = 0; mi < 2; mi++)
#pragma unroll
                for (int ni = 0; ni < 8; ni++) MMA16816(acc[mi][ni], af[mi], bf[ni]);
        }
    }

    // ---- fused LayerNorm over 256 cols ----
    __syncthreads();
    float2* part = (float2*)smem;  // [64 rows][4 wn]
    const int g = lane >> 2, q = lane & 3;
#pragma unroll
    for (int mi = 0; mi < 2; mi++) {
        float s0 = 0.f, ss0 = 0.f, s8 = 0.f, ss8 = 0.f;
#pragma unroll
        for (int ni = 0; ni < 8; ni++) {
            float v0 = acc[mi][ni][0], v1 = acc[mi][ni][1];
            float v2 = acc[mi][ni][2], v3 = acc[mi][ni][3];
            s0 += v0 + v1; ss0 += v0 * v0 + v1 * v1;
            s8 += v2 + v3; ss8 += v2 * v2 + v3 * v3;
        }
#pragma unroll
        for (int o = 1; o < 4; o <<= 1) {
            s0 += __shfl_xor_sync(0xffffffffu, s0, o);
            ss0 += __shfl_xor_sync(0xffffffffu, ss0, o);
            s8 += __shfl_xor_sync(0xffffffffu, s8, o);
            ss8 += __shfl_xor_sync(0xffffffffu, ss8, o);
        }
        if (q == 0) {
            int lr = wm * 32 + mi * 16 + g;
            part[lr * 4 + wn] = make_float2(s0, ss0);
            part[(lr + 8) * 4 + wn] = make_float2(s8, ss8);
        }
    }
    __syncthreads();
#pragma unroll
    for (int mi = 0; mi < 2; mi++) {
        int lr = wm * 32 + mi * 16 + g;
        float2 a0 = part[lr * 4 + 0], a1 = part[lr * 4 + 1];
        float2 a2 = part[lr * 4 + 2], a3 = part[lr * 4 + 3];
        float s = a0.x + a1.x + a2.x + a3.x;
        float ss = a0.y + a1.y + a2.y + a3.y;
        float mean0 = s * (1.f / 256.f);
        float rstd0 = rsqrtf(ss * (1.f / 256.f) - mean0 * mean0 + 1e-5f);
        a0 = part[(lr + 8) * 4 + 0]; a1 = part[(lr + 8) * 4 + 1];
        a2 = part[(lr + 8) * 4 + 2]; a3 = part[(lr + 8) * 4 + 3];
        s = a0.x + a1.x + a2.x + a3.x;
        ss = a0.y + a1.y + a2.y + a3.y;
        float mean8 = s * (1.f / 256.f);
        float rstd8 = rsqrtf(ss * (1.f / 256.f) - mean8 * mean8 + 1e-5f);
        int r0 = m0 + lr;
#pragma unroll
        for (int ni = 0; ni < 8; ni++) {
            int col = wn * 64 + ni * 8 + 2 * q;
            float2 gg = *(const float2*)(gamma + col);
            float2 bb = *(const float2*)(beta + col);
            float v0 = fmaxf((acc[mi][ni][0] - mean0) * rstd0 * gg.x + bb.x, 0.f);
            float v1 = fmaxf((acc[mi][ni][1] - mean0) * rstd0 * gg.y + bb.y, 0.f);
            float v2 = fmaxf((acc[mi][ni][2] - mean8) * rstd8 * gg.x + bb.x, 0.f);
            float v3 = fmaxf((acc[mi][ni][3] - mean8) * rstd8 * gg.y + bb.y, 0.f);
            __half2 h0 = __floats2half2_rn(v0, v1);
            __half2 h1 = __floats2half2_rn(v2, v3);
            *(__half2*)(Ch + (size_t)r0 * CAT + H4 + col) = h0;
            *(__half2*)(Ch + (size_t)(r0 + 8) * CAT + H4 + col) = h1;
        }
    }
}

// ---------------- readout normalize ----------------
__global__ void k_norm(float* __restrict__ out) {
    int b = blockIdx.x;
    int t = threadIdx.x;  // 128 threads
    float v = g_readout[b * OUTD + t];
    float ss = v * v;
#pragma unroll
    for (int o = 16; o > 0; o >>= 1) ss += __shfl_xor_sync(0xffffffffu, ss, o);
    __shared__ float sw[4];
    if ((t & 31) == 0) sw[t >> 5] = ss;
    __syncthreads();
    float tot = sw[0] + sw[1] + sw[2] + sw[3];
    float norm = fmaxf(sqrtf(tot), 1e-12f);
    out[b * OUTD + t] = v / norm;
}

// ---------------- launch ----------------
extern "C" void kernel_launch(void* const* d_in, const int* in_sizes, int n_in,
                              void* d_out, int out_size) {
    const float* x    = (const float*)d_in[0];
    const float* w    = (const float*)d_in[1];
    const float* W1   = (const float*)d_in[2];
    const float* fc1W = (const float*)d_in[3];
    const float* gam  = (const float*)d_in[4];
    const float* bet  = (const float*)d_in[5];
    const float* W2   = (const float*)d_in[6];
    const float* W3   = (const float*)d_in[7];
    const int*   src  = (const int*)d_in[8];
    const int*   dst  = (const int*)d_in[9];
    const int*   gid  = (const int*)d_in[10];
    float* out = (float*)d_out;

    __half *p_bh, *p_xh, *p_a1, *p_c, *p_y2, *p_x2, *p_y3;
    cudaGetSymbolAddress((void**)&p_bh, g_bh);
    cudaGetSymbolAddress((void**)&p_xh, g_xh);
    cudaGetSymbolAddress((void**)&p_a1, g_a1);
    cudaGetSymbolAddress((void**)&p_c, g_c);
    cudaGetSymbolAddress((void**)&p_y2, g_y2);
    cudaGetSymbolAddress((void**)&p_x2, g_x2);
    cudaGetSymbolAddress((void**)&p_y3, g_y3);

    const int SMEM = 61440;
    const int SMEM_FC1 = 76800;
    cudaFuncSetAttribute(k_mma<128, 1>, cudaFuncAttributeMaxDynamicSharedMemorySize, SMEM);
    cudaFuncSetAttribute(k_mma<512, 2>, cudaFuncAttributeMaxDynamicSharedMemorySize, SMEM);
    cudaFuncSetAttribute(k_mma<256, 2>, cudaFuncAttributeMaxDynamicSharedMemorySize, SMEM);
    cudaFuncSetAttribute(k_mma_fc1, cudaFuncAttributeMaxDynamicSharedMemorySize, SMEM_FC1);

    // side stream + events (created once, on first — non-capture — call)
    static cudaStream_t s_fc1 = nullptr;
    static cudaEvent_t ev_conv = nullptr, ev_fc1 = nullptr;
    if (s_fc1 == nullptr) {
        cudaStreamCreateWithFlags(&s_fc1, cudaStreamNonBlocking);
        cudaEventCreateWithFlags(&ev_conv, cudaEventDisableTiming);
        cudaEventCreateWithFlags(&ev_fc1, cudaEventDisableTiming);
    }

    const int TB = 256;
    const int AGG_BLK = (NP * 32 + TB - 1) / TB;
    const int GX = NP / 128;   // 313
    const int GX64 = NP / 64;  // 626

    // preprocessing (main stream)
    k_zero_conv<<<(WTOT + NP * IND + TB - 1) / TB, TB>>>(W1, fc1W, W2, W3, x);
    // fork: fc1 GEMM depends only on zero_conv — run on side stream
    cudaEventRecord(ev_conv, 0);
    cudaStreamWaitEvent(s_fc1, ev_conv, 0);
    k_mma_fc1<<<GX64, TB, SMEM_FC1, s_fc1>>>(p_xh, p_bh + 32768, p_c, gam, bet);
    cudaEventRecord(ev_fc1, s_fc1);

    // main chain
    k_deg<<<(NE + TB - 1) / TB, TB>>>(src, dst);
    k_scan_a<<<40, 1024>>>();
    k_scan_c<<<40, 1024>>>();
    k_place<<<(NE + TB - 1) / TB, TB>>>(src, dst, w);
    // layer 1: agg(x_fp16) -> fp16 plane, GEMM 128->256 relu+fp16 into cat[:,0:256)
    k_agg<IND, 0><<<AGG_BLK, TB>>>(p_xh, p_a1, nullptr);
    k_mma<128, 1><<<dim3(GX, 2), TB, SMEM>>>(p_a1, p_bh + 0, p_c, CAT, 0);
    // join: layer-2 GEMM consumes the full concat
    cudaStreamWaitEvent(0, ev_fc1, 0);
    k_mma<512, 2><<<dim3(GX, 2), TB, SMEM>>>(p_c, p_bh + 65536, p_y2, H4, 0);
    k_agg<H4, 1><<<AGG_BLK, TB>>>(p_y2, p_x2, nullptr);
    // layer 3: GEMM 256->128 raw fp16, agg(fp16) + relu + readout
    k_mma<256, 2><<<dim3(GX, 1), TB, SMEM>>>(p_x2, p_bh + 196608, p_y3, OUTD, 0);
    k_agg<OUTD, 2><<<AGG_BLK, TB>>>(p_y3, nullptr, gid);
    // final L2 normalize
    k_norm<<<NG, OUTD>>>(out);
}

// round 12
// speedup vs baseline: 1.2620x; 1.0032x over previous
#include <cuda_runtime.h>
#include <cuda_fp16.h>
#include <cstdint>

#define NN 40000
#define NP 40064   // 313 * 128, padded row count
#define NE 320000
#define NG 64
#define IND 128
#define H4 256
#define OUTD 128
#define CAT 512
#define SFLAG (1 << 30)

// ---------------- scratch (device globals; no allocation allowed) ----------------
__device__ int   g_outcnt[NN];
__device__ int   g_incnt[NN];
__device__ int   g_cursor[NN];
__device__ int   g_rowptr[NN + 1];
__device__ int   g_bsum[40];
__device__ float g_outinv[NN];
__device__ float g_ininv[NN];
__device__ int2  g_ep[NE];           // packed {src, coef_bits}, CSR-ordered by dst
__device__ float g_readout[NG * OUTD];
// fp16 activations (padded to NP rows)
__device__ __half g_xh[NP * IND];    // x as fp16
__device__ __half g_y1[NP * H4];     // layer1 GEMM out (pre-agg)
__device__ __half g_c[NP * CAT];     // concat [x1 | f1]
__device__ __half g_y2[NP * H4];     // layer2 GEMM out (pre-agg)
__device__ __half g_x2[NP * H4];     // x2
__device__ __half g_y3[NP * OUTD];   // layer3 GEMM out (pre-agg)
// weights fp16, transposed to [N][K]
// layout: W1 @0 (32768), fc1 @32768 (32768), W2 @65536 (131072), W3 @196608 (32768)
__device__ __half g_bh[229376];

// ---------------- helpers ----------------
template <int V> struct VecSel;
template <> struct VecSel<2> { using T = uint2; };
template <> struct VecSel<4> { using T = uint4; };

__device__ __forceinline__ uint32_t smem_u32(const void* p) {
    uint32_t a;
    asm("{ .reg .u64 t; cvta.to.shared.u64 t, %1; cvt.u32.u64 %0, t; }" : "=r"(a) : "l"(p));
    return a;
}
__device__ __forceinline__ void cpa16(uint32_t dst, const void* src) {
    asm volatile("cp.async.cg.shared.global [%0], [%1], 16;" :: "r"(dst), "l"(src) : "memory");
}
__device__ __forceinline__ void cpa_commit() {
    asm volatile("cp.async.commit_group;" ::: "memory");
}
#define MMA16816(d, a, b)                                                     \
    asm volatile(                                                             \
        "mma.sync.aligned.m16n8k16.row.col.f32.f16.f16.f32 "                  \
        "{%0,%1,%2,%3}, {%4,%5,%6,%7}, {%8,%9}, {%0,%1,%2,%3};"               \
        : "+f"((d)[0]), "+f"((d)[1]), "+f"((d)[2]), "+f"((d)[3])              \
        : "r"((a)[0]), "r"((a)[1]), "r"((a)[2]), "r"((a)[3]),                 \
          "r"((b)[0]), "r"((b)[1]))
#define LDSM4(R, addr)                                                        \
    asm volatile("ldmatrix.sync.aligned.m8n8.x4.shared.b16 {%0,%1,%2,%3}, [%4];" \
        : "=r"((R)[0]), "=r"((R)[1]), "=r"((R)[2]), "=r"((R)[3]) : "r"(addr))

// ---------------- setup kernels ----------------
__global__ void k_zero() {
    int i = blockIdx.x * blockDim.x + threadIdx.x;
    if (i < NN) { g_outcnt[i] = 0; g_incnt[i] = 0; g_cursor[i] = 0; }
    if (i < NG * OUTD) g_readout[i] = 0.f;
    if (i < 40) g_bsum[i] = 0;
}

#define WTOT 229376
__global__ void k_conv(const float* __restrict__ W1, const float* __restrict__ F1,
                       const float* __restrict__ W2, const float* __restrict__ W3,
                       const float* __restrict__ x) {
    int idx = blockIdx.x * blockDim.x + threadIdx.x;
    if (idx < WTOT) {
        const float* W; int K, N, base;
        if (idx < 32768)       { W = W1; K = 128; N = 256; base = 0; }
        else if (idx < 65536)  { W = F1; K = 128; N = 256; base = 32768; }
        else if (idx < 196608) { W = W2; K = 512; N = 256; base = 65536; }
        else                   { W = W3; K = 256; N = 128; base = 196608; }
        int li = idx - base;
        int k = li % K, n = li / K;
        g_bh[idx] = __float2half_rn(W[k * N + n]);
    } else {
        int j = idx - WTOT;
        if (j < NP * IND) {
            float v = (j < NN * IND) ? x[j] : 0.f;
            g_xh[j] = __float2half_rn(v);
        }
    }
}

__global__ void k_deg(const int* __restrict__ src, const int* __restrict__ dst) {
    int e = blockIdx.x * blockDim.x + threadIdx.x;
    if (e < NE) {
        atomicAdd(&g_outcnt[src[e]], 1);
        atomicAdd(&g_incnt[dst[e]], 1);
    }
}

// fused scan: per-block scan + single-word atomic publish + parallel lookback
__global__ void k_scan() {
    __shared__ int sh[1024];
    __shared__ int pvals[40];
    __shared__ int pre;
    int b = blockIdx.x, t = threadIdx.x;
    int idx = b * 1024 + t;
    int v = (idx < NN) ? g_incnt[idx] : 0;
    if (idx < NN) {
        g_ininv[idx]  = rsqrtf((float)max(v, 1));
        g_outinv[idx] = rsqrtf((float)max(g_outcnt[idx], 1));
    }
    sh[t] = v;
    __syncthreads();
#pragma unroll
    for (int off = 1; off < 1024; off <<= 1) {
        int u = (t >= off) ? sh[t - off] : 0;
        __syncthreads();
        sh[t] += u;
        __syncthreads();
    }
    int incl = sh[t];
    if (t == 1023) atomicExch(&g_bsum[b], incl | SFLAG);  // publish block aggregate
    if (t < b) {  // parallel lookback: one thread polls each predecessor
        int a;
        do { a = atomicAdd(&g_bsum[t], 0); } while (!(a & SFLAG));
        pvals[t] = a & ~SFLAG;
    }
    __syncthreads();
    if (t == 0) {
        int s = 0;
        for (int i = 0; i < b; i++) s += pvals[i];
        pre = s;
    }
    __syncthreads();
    if (idx <= NN) g_rowptr[idx] = incl - v + pre;
}

__global__ void k_place(const int* __restrict__ src, const int* __restrict__ dst,
                        const float* __restrict__ w) {
    int e = blockIdx.x * blockDim.x + threadIdx.x;
    if (e >= NE) return;
    float4 ww = *(const float4*)(w + 4 * e);
    float m = fmaxf(fmaxf(ww.x, ww.y), fmaxf(ww.z, ww.w));
    int d = dst[e];
    int s = src[e];
    int pos = g_rowptr[d] + atomicAdd(&g_cursor[d], 1);
    g_ep[pos] = make_int2(s, __float_as_int(m * g_outinv[s]));
}

// ---------------- aggregation: one warp per dst node, vectorized fp16 gather ----------------
// MODE 1: relu + fp16 out (strided); MODE 2: relu + readout atomics
template <int D, int MODE>
__global__ void k_agg(const __half* __restrict__ in, __half* __restrict__ oh,
                      int ldO, int oOff, const int* __restrict__ gid) {
    constexpr int V = D / 64;  // uint32 (half2) units per lane
    using VT = typename VecSel<V>::T;
    int warp = (blockIdx.x * blockDim.x + threadIdx.x) >> 5;
    int lane = threadIdx.x & 31;
    if (warp >= NP) return;
    if (warp >= NN) {
        if (MODE != 2) {
            VT z = {};
            ((VT*)(oh + (size_t)warp * ldO + oOff))[lane] = z;
        }
        return;
    }
    int beg = g_rowptr[warp];
    int end = g_rowptr[warp + 1];
    float2 acc[V];
#pragma unroll
    for (int v = 0; v < V; v++) acc[v] = make_float2(0.f, 0.f);
    int e = beg;
    for (; e + 3 < end; e += 4) {  // 4-way unroll for MLP
        int2 p0 = g_ep[e], p1 = g_ep[e + 1], p2 = g_ep[e + 2], p3 = g_ep[e + 3];
        VT t0 = ((const VT*)(in + (size_t)p0.x * D))[lane];
        VT t1 = ((const VT*)(in + (size_t)p1.x * D))[lane];
        VT t2 = ((const VT*)(in + (size_t)p2.x * D))[lane];
        VT t3 = ((const VT*)(in + (size_t)p3.x * D))[lane];
        float c0 = __int_as_float(p0.y), c1 = __int_as_float(p1.y);
        float c2 = __int_as_float(p2.y), c3 = __int_as_float(p3.y);
        const uint32_t* w0 = (const uint32_t*)&t0;
        const uint32_t* w1 = (const uint32_t*)&t1;
        const uint32_t* w2 = (const uint32_t*)&t2;
        const uint32_t* w3 = (const uint32_t*)&t3;
#pragma unroll
        for (int v = 0; v < V; v++) {
            float2 f0 = __half22float2(*(const __half2*)&w0[v]);
            float2 f1 = __half22float2(*(const __half2*)&w1[v]);
            float2 f2 = __half22float2(*(const __half2*)&w2[v]);
            float2 f3 = __half22float2(*(const __half2*)&w3[v]);
            acc[v].x = fmaf(c0, f0.x, fmaf(c1, f1.x, fmaf(c2, f2.x, fmaf(c3, f3.x, acc[v].x))));
            acc[v].y = fmaf(c0, f0.y, fmaf(c1, f1.y, fmaf(c2, f2.y, fmaf(c3, f3.y, acc[v].y))));
        }
    }
    for (; e < end; e++) {
        int2 p = g_ep[e];
        float c = __int_as_float(p.y);
        VT t = ((const VT*)(in + (size_t)p.x * D))[lane];
        const uint32_t* w = (const uint32_t*)&t;
#pragma unroll
        for (int v = 0; v < V; v++) {
            float2 f = __half22float2(*(const __half2*)&w[v]);
            acc[v].x = fmaf(c, f.x, acc[v].x);
            acc[v].y = fmaf(c, f.y, acc[v].y);
        }
    }
    float inv = g_ininv[warp];
#pragma unroll
    for (int v = 0; v < V; v++) {
        acc[v].x = fmaxf(acc[v].x * inv, 0.f);
        acc[v].y = fmaxf(acc[v].y * inv, 0.f);
    }
    if (MODE == 2) {
        int g = gid[warp];
        float* r = g_readout + g * OUTD + lane * 4;
        atomicAdd(r + 0, acc[0].x);
        atomicAdd(r + 1, acc[0].y);
        atomicAdd(r + 2, acc[1].x);
        atomicAdd(r + 3, acc[1].y);
    } else {
        VT ov;
        uint32_t* ow = (uint32_t*)&ov;
#pragma unroll
        for (int v = 0; v < V; v++) {
            __half2 a = __floats2half2_rn(acc[v].x, acc[v].y);
            ow[v] = *(uint32_t*)&a;
        }
        ((VT*)(oh + (size_t)warp * ldO + oOff))[lane] = ov;
    }
}

// ---------------- fp16 single-pass mma.sync GEMM, 3-stage pipeline ----------------
// Block tile 128x128, BK=32/stage, 3 stages, one sync per chunk. 80B-padded smem rows.
template <int K>
__global__ __launch_bounds__(256, 2) void k_mma(
    const __half* __restrict__ Ah, const __half* __restrict__ Bh,
    __half* __restrict__ Ch, int ldC, int colOff) {
    extern __shared__ __align__(16) uint8_t smem[];
    constexpr int NC = K / 32;
    constexpr uint32_t AH_ = 0, BH_ = 10240, STG = 20480;
    const int tid = threadIdx.x;
    const int wid = tid >> 5, lane = tid & 31;
    const int wm = wid & 3, wn = wid >> 2;
    const int m0 = blockIdx.x * 128;
    const int nblk = blockIdx.y * 128;
    const uint32_t sb = smem_u32(smem);

    float acc[2][8][4];
#pragma unroll
    for (int mi = 0; mi < 2; mi++)
#pragma unroll
        for (int ni = 0; ni < 8; ni++)
#pragma unroll
            for (int r = 0; r < 4; r++) acc[mi][ni][r] = 0.f;

    const int lrow = tid & 127;
    const bool isB = tid >= 128;
    const __half* gS = isB ? (Bh + (size_t)(nblk + lrow) * K)
                           : (Ah + (size_t)(m0 + lrow) * K);
    const uint32_t gD = (isB ? BH_ : AH_) + (uint32_t)lrow * 80;

    const uint32_t aoff = AH_ + (uint32_t)(wm * 32 + (lane & 7) + ((lane >> 3) & 1) * 8) * 80 +
                          (lane >> 4) * 16;
    const uint32_t boff = BH_ + (uint32_t)(wn * 64 + ((lane >> 4) & 1) * 8 + (lane & 7)) * 80 +
                          ((lane >> 3) & 1) * 16;

    {
        uint32_t st = sb;
        const __half* gp = gS;
#pragma unroll
        for (int j = 0; j < 4; j++) cpa16(st + gD + j * 16, gp + j * 8);
        cpa_commit();
        st = sb + STG;
        gp = gS + 32;
#pragma unroll
        for (int j = 0; j < 4; j++) cpa16(st + gD + j * 16, gp + j * 8);
        cpa_commit();
    }

    for (int c = 0; c < NC; c++) {
        if (c + 1 < NC)
            asm volatile("cp.async.wait_group 1;" ::: "memory");
        else
            asm volatile("cp.async.wait_group 0;" ::: "memory");
        __syncthreads();
        if (c + 2 < NC) {
            uint32_t st = sb + ((c + 2) % 3) * STG;
            const __half* gp = gS + (c + 2) * 32;
#pragma unroll
            for (int j = 0; j < 4; j++) cpa16(st + gD + j * 16, gp + j * 8);
            cpa_commit();
        }
        uint32_t st = sb + (c % 3) * STG;
#pragma unroll
        for (int kk = 0; kk < 2; kk++) {
            const uint32_t ko = kk * 32;
            uint32_t af[2][4], bf[8][2];
#pragma unroll
            for (int mi = 0; mi < 2; mi++) LDSM4(af[mi], st + aoff + mi * 1280 + ko);
#pragma unroll
            for (int p = 0; p < 4; p++) {
                uint32_t r4[4];
                LDSM4(r4, st + boff + p * 1280 + ko);
                bf[2 * p][0] = r4[0]; bf[2 * p][1] = r4[1];
                bf[2 * p + 1][0] = r4[2]; bf[2 * p + 1][1] = r4[3];
            }
#pragma unroll
            for (int mi = 0; mi < 2; mi++)
#pragma unroll
                for (int ni = 0; ni < 8; ni++) MMA16816(acc[mi][ni], af[mi], bf[ni]);
        }
    }

    const int g = lane >> 2, q = lane & 3;
#pragma unroll
    for (int mi = 0; mi < 2; mi++)
#pragma unroll
        for (int ni = 0; ni < 8; ni++) {
            int r0 = m0 + wm * 32 + mi * 16 + g;
            int cc = colOff + nblk + wn * 64 + ni * 8 + 2 * q;
            __half2 a = __floats2half2_rn(acc[mi][ni][0], acc[mi][ni][1]);
            __half2 b = __floats2half2_rn(acc[mi][ni][2], acc[mi][ni][3]);
            *(__half2*)(Ch + (size_t)r0 * ldC + cc) = a;
            *(__half2*)(Ch + (size_t)(r0 + 8) * ldC + cc) = b;
        }
}

// ---------------- fc1 GEMM (K=128, full N=256 per CTA) + fused LayerNorm + ReLU ----------------
__global__ __launch_bounds__(256, 2) void k_mma_fc1(
    const __half* __restrict__ Ah, const __half* __restrict__ Bh,
    __half* __restrict__ Ch,
    const float* __restrict__ gamma, const float* __restrict__ beta) {
    extern __shared__ __align__(16) uint8_t smem[];
    constexpr int NC = 4;  // K=128 / 32
    constexpr uint32_t AH_ = 0, BH_ = 5120, STG = 25600;
    const int tid = threadIdx.x;
    const int wid = tid >> 5, lane = tid & 31;
    const int wm = wid & 1, wn = wid >> 1;  // 2 x 4
    const int m0 = blockIdx.x * 64;
    const uint32_t sb = smem_u32(smem);

    float acc[2][8][4];
#pragma unroll
    for (int mi = 0; mi < 2; mi++)
#pragma unroll
        for (int ni = 0; ni < 8; ni++)
#pragma unroll
            for (int r = 0; r < 4; r++) acc[mi][ni][r] = 0.f;

    const __half* bSrc = Bh + (size_t)tid * 128;
    const uint32_t bDst = BH_ + (uint32_t)tid * 80;
    const __half* aSrc = Ah + (size_t)(m0 + tid) * 128;
    const uint32_t aDst = AH_ + (uint32_t)tid * 80;
    const bool isA = tid < 64;

    const uint32_t aoff = AH_ + (uint32_t)(wm * 32 + (lane & 7) + ((lane >> 3) & 1) * 8) * 80 +
                          (lane >> 4) * 16;
    const uint32_t boff = BH_ + (uint32_t)(wn * 64 + ((lane >> 4) & 1) * 8 + (lane & 7)) * 80 +
                          ((lane >> 3) & 1) * 16;

#pragma unroll
    for (int s = 0; s < 2; s++) {
        uint32_t st = sb + s * STG;
#pragma unroll
        for (int j = 0; j < 4; j++) cpa16(st + bDst + j * 16, bSrc + s * 32 + j * 8);
        if (isA)
#pragma unroll
            for (int j = 0; j < 4; j++) cpa16(st + aDst + j * 16, aSrc + s * 32 + j * 8);
        cpa_commit();
    }

    for (int c = 0; c < NC; c++) {
        if (c + 1 < NC)
            asm volatile("cp.async.wait_group 1;" ::: "memory");
        else
            asm volatile("cp.async.wait_group 0;" ::: "memory");
        __syncthreads();
        if (c + 2 < NC) {
            uint32_t st = sb + ((c + 2) % 3) * STG;
#pragma unroll
            for (int j = 0; j < 4; j++) cpa16(st + bDst + j * 16, bSrc + (c + 2) * 32 + j * 8);
            if (isA)
#pragma unroll
                for (int j = 0; j < 4; j++) cpa16(st + aDst + j * 16, aSrc + (c + 2) * 32 + j * 8);
            cpa_commit();
        }
        uint32_t st = sb + (c % 3) * STG;
#pragma unroll
        for (int kk = 0; kk < 2; kk++) {
            const uint32_t ko = kk * 32;
            uint32_t af[2][4], bf[8][2];
#pragma unroll
            for (int mi = 0; mi < 2; mi++) LDSM4(af[mi], st + aoff + mi * 1280 + ko);
#pragma unroll
            for (int p = 0; p < 4; p++) {
                uint32_t r4[4];
                LDSM4(r4, st + boff + p * 1280 + ko);
                bf[2 * p][0] = r4[0]; bf[2 * p][1] = r4[1];
                bf[2 * p + 1][0] = r4[2]; bf[2 * p + 1][1] = r4[3];
            }
#pragma unroll
            for (int mi = 0; mi < 2; mi++)
#pragma unroll
                for (int ni = 0; ni < 8; ni++) MMA16816(acc[mi][ni], af[mi], bf[ni]);
        }
    }

    // ---- fused LayerNorm over 256 cols ----
    __syncthreads();
    float2* part = (float2*)smem;  // [64 rows][4 wn]
    const int g = lane >> 2, q = lane & 3;
#pragma unroll
    for (int mi = 0; mi < 2; mi++) {
        float s0 = 0.f, ss0 = 0.f, s8 = 0.f, ss8 = 0.f;
#pragma unroll
        for (int ni = 0; ni < 8; ni++) {
            float v0 = acc[mi][ni][0], v1 = acc[mi][ni][1];
            float v2 = acc[mi][ni][2], v3 = acc[mi][ni][3];
            s0 += v0 + v1; ss0 += v0 * v0 + v1 * v1;
            s8 += v2 + v3; ss8 += v2 * v2 + v3 * v3;
        }
#pragma unroll
        for (int o = 1; o < 4; o <<= 1) {
            s0 += __shfl_xor_sync(0xffffffffu, s0, o);
            ss0 += __shfl_xor_sync(0xffffffffu, ss0, o);
            s8 += __shfl_xor_sync(0xffffffffu, s8, o);
            ss8 += __shfl_xor_sync(0xffffffffu, ss8, o);
        }
        if (q == 0) {
            int lr = wm * 32 + mi * 16 + g;
            part[lr * 4 + wn] = make_float2(s0, ss0);
            part[(lr + 8) * 4 + wn] = make_float2(s8, ss8);
        }
    }
    __syncthreads();
#pragma unroll
    for (int mi = 0; mi < 2; mi++) {
        int lr = wm * 32 + mi * 16 + g;
        float2 a0 = part[lr * 4 + 0], a1 = part[lr * 4 + 1];
        float2 a2 = part[lr * 4 + 2], a3 = part[lr * 4 + 3];
        float s = a0.x + a1.x + a2.x + a3.x;
        float ss = a0.y + a1.y + a2.y + a3.y;
        float mean0 = s * (1.f / 256.f);
        float rstd0 = rsqrtf(ss * (1.f / 256.f) - mean0 * mean0 + 1e-5f);
        a0 = part[(lr + 8) * 4 + 0]; a1 = part[(lr + 8) * 4 + 1];
        a2 = part[(lr + 8) * 4 + 2]; a3 = part[(lr + 8) * 4 + 3];
        s = a0.x + a1.x + a2.x + a3.x;
        ss = a0.y + a1.y + a2.y + a3.y;
        float mean8 = s * (1.f / 256.f);
        float rstd8 = rsqrtf(ss * (1.f / 256.f) - mean8 * mean8 + 1e-5f);
        int r0 = m0 + lr;
#pragma unroll
        for (int ni = 0; ni < 8; ni++) {
            int col = wn * 64 + ni * 8 + 2 * q;
            float2 gg = *(const float2*)(gamma + col);
            float2 bb = *(const float2*)(beta + col);
            float v0 = fmaxf((acc[mi][ni][0] - mean0) * rstd0 * gg.x + bb.x, 0.f);
            float v1 = fmaxf((acc[mi][ni][1] - mean0) * rstd0 * gg.y + bb.y, 0.f);
            float v2 = fmaxf((acc[mi][ni][2] - mean8) * rstd8 * gg.x + bb.x, 0.f);
            float v3 = fmaxf((acc[mi][ni][3] - mean8) * rstd8 * gg.y + bb.y, 0.f);
            __half2 h0 = __floats2half2_rn(v0, v1);
            __half2 h1 = __floats2half2_rn(v2, v3);
            *(__half2*)(Ch + (size_t)r0 * CAT + H4 + col) = h0;
            *(__half2*)(Ch + (size_t)(r0 + 8) * CAT + H4 + col) = h1;
        }
    }
}

// ---------------- readout normalize ----------------
__global__ void k_norm(float* __restrict__ out) {
    int b = blockIdx.x;
    int t = threadIdx.x;  // 128 threads
    float v = g_readout[b * OUTD + t];
    float ss = v * v;
#pragma unroll
    for (int o = 16; o > 0; o >>= 1) ss += __shfl_xor_sync(0xffffffffu, ss, o);
    __shared__ float sw[4];
    if ((t & 31) == 0) sw[t >> 5] = ss;
    __syncthreads();
    float tot = sw[0] + sw[1] + sw[2] + sw[3];
    float norm = fmaxf(sqrtf(tot), 1e-12f);
    out[b * OUTD + t] = v / norm;
}

// ---------------- launch ----------------
extern "C" void kernel_launch(void* const* d_in, const int* in_sizes, int n_in,
                              void* d_out, int out_size) {
    const float* x    = (const float*)d_in[0];
    const float* w    = (const float*)d_in[1];
    const float* W1   = (const float*)d_in[2];
    const float* fc1W = (const float*)d_in[3];
    const float* gam  = (const float*)d_in[4];
    const float* bet  = (const float*)d_in[5];
    const float* W2   = (const float*)d_in[6];
    const float* W3   = (const float*)d_in[7];
    const int*   src  = (const int*)d_in[8];
    const int*   dst  = (const int*)d_in[9];
    const int*   gid  = (const int*)d_in[10];
    float* out = (float*)d_out;

    __half *p_bh, *p_xh, *p_y1, *p_c, *p_y2, *p_x2, *p_y3;
    cudaGetSymbolAddress((void**)&p_bh, g_bh);
    cudaGetSymbolAddress((void**)&p_xh, g_xh);
    cudaGetSymbolAddress((void**)&p_y1, g_y1);
    cudaGetSymbolAddress((void**)&p_c, g_c);
    cudaGetSymbolAddress((void**)&p_y2, g_y2);
    cudaGetSymbolAddress((void**)&p_x2, g_x2);
    cudaGetSymbolAddress((void**)&p_y3, g_y3);

    const int SMEM = 61440;
    const int SMEM_FC1 = 76800;
    cudaFuncSetAttribute(k_mma<128>, cudaFuncAttributeMaxDynamicSharedMemorySize, SMEM);
    cudaFuncSetAttribute(k_mma<512>, cudaFuncAttributeMaxDynamicSharedMemorySize, SMEM);
    cudaFuncSetAttribute(k_mma<256>, cudaFuncAttributeMaxDynamicSharedMemorySize, SMEM);
    cudaFuncSetAttribute(k_mma_fc1, cudaFuncAttributeMaxDynamicSharedMemorySize, SMEM_FC1);

    // side streams + events (created once, on first — non-capture — call)
    static cudaStream_t s1 = nullptr, s2 = nullptr;
    static cudaEvent_t ev_conv = nullptr, ev_g1 = nullptr, ev_fc1 = nullptr;
    if (s1 == nullptr) {
        cudaStreamCreateWithFlags(&s1, cudaStreamNonBlocking);
        cudaStreamCreateWithFlags(&s2, cudaStreamNonBlocking);
        cudaEventCreateWithFlags(&ev_conv, cudaEventDisableTiming);
        cudaEventCreateWithFlags(&ev_g1, cudaEventDisableTiming);
        cudaEventCreateWithFlags(&ev_fc1, cudaEventDisableTiming);
    }

    const int TB = 256;
    const int AGG_BLK = (NP * 32 + TB - 1) / TB;
    const int GX = NP / 128;   // 313
    const int GX64 = NP / 64;  // 626

    // ---- fork point: everything forks from the main stream's capture origin ----
    // side stream 1: conversion, then layer-1 GEMM (y1 = xh @ W1; graph-independent)
    cudaEventRecord(ev_conv, 0);  // marks capture-origin dependency for s1/s2
    cudaStreamWaitEvent(s1, ev_conv, 0);
    k_conv<<<(WTOT + NP * IND + TB - 1) / TB, TB, 0, s1>>>(W1, fc1W, W2, W3, x);
    k_mma<128><<<dim3(GX, 2), TB, SMEM, s1>>>(p_xh, p_bh + 0, p_y1, H4, 0);
    cudaEventRecord(ev_g1, s1);
    // side stream 2: fc1 GEMM + fused LN (needs conv output) — fork after conv
    cudaStreamWaitEvent(s2, ev_g1, 0);  // conv+gemm1 done => conv done
    k_mma_fc1<<<GX64, TB, SMEM_FC1, s2>>>(p_xh, p_bh + 32768, p_c, gam, bet);
    cudaEventRecord(ev_fc1, s2);

    // main chain: CSR build
    k_zero<<<(NN + TB - 1) / TB, TB>>>();
    k_deg<<<(NE + TB - 1) / TB, TB>>>(src, dst);
    k_scan<<<40, 1024>>>();
    k_place<<<(NE + TB - 1) / TB, TB>>>(src, dst, w);
    // layer 1 aggregation: gather y1 (256-d), relu, write concat cols [0,256)
    cudaStreamWaitEvent(0, ev_g1, 0);
    k_agg<H4, 1><<<AGG_BLK, TB>>>(p_y1, p_c, CAT, 0, nullptr);
    // join fc1, then layer 2: GEMM 512->256, agg + relu
    cudaStreamWaitEvent(0, ev_fc1, 0);
    k_mma<512><<<dim3(GX, 2), TB, SMEM>>>(p_c, p_bh + 65536, p_y2, H4, 0);
    k_agg<H4, 1><<<AGG_BLK, TB>>>(p_y2, p_x2, H4, 0, nullptr);
    // layer 3: GEMM 256->128, agg + relu + readout
    k_mma<256><<<dim3(GX, 1), TB, SMEM>>>(p_x2, p_bh + 196608, p_y3, OUTD, 0);
    k_agg<OUTD, 2><<<AGG_BLK, TB>>>(p_y3, nullptr, 0, 0, gid);
    // final L2 normalize
    k_norm<<<NG, OUTD>>>(out);
}